// round 5
// baseline (speedup 1.0000x reference)
#include <cuda_runtime.h>
#include <cuda_bf16.h>
#include <cstdint>

// ---------------- problem constants ----------------
#define NODE_DIM 128
#define CTX_DIM  256
#define OUT_DIM  256
#define IN_DIM   384
#define K_TOTAL  3072          // 384 * 8 : k = 8*i + j (j=0 silu, j=1..7 spline coefs)
#define MAX_EDGES 100000

typedef __nv_bfloat16 bf16;

// ---------------- device scratch (static) ----------------
__device__ float g_xc[(size_t)MAX_EDGES * NODE_DIM];
__device__ bf16  g_w_hi[(size_t)OUT_DIM * K_TOTAL];
__device__ bf16  g_w_lo[(size_t)OUT_DIM * K_TOTAL];
__device__ bf16  g_cemb_hi[(size_t)MAX_EDGES * CTX_DIM];
__device__ bf16  g_cemb_lo[(size_t)MAX_EDGES * CTX_DIM];
__device__ bf16  g_cw_hi[(size_t)NODE_DIM * CTX_DIM];
__device__ bf16  g_cw_lo[(size_t)NODE_DIM * CTX_DIM];

// ---------------- helpers ----------------
__device__ __forceinline__ uint32_t smem_u32(const void* p) {
    uint32_t a;
    asm("{ .reg .u64 t; cvta.to.shared.u64 t, %1; cvt.u32.u64 %0, t; }" : "=r"(a) : "l"(p));
    return a;
}
#define SWZ(x) ((x) ^ (((x) >> 3) & 0x70))

__device__ __forceinline__ void cp16(uint32_t saddr, const void* g, uint32_t sz) {
    asm volatile("cp.async.cg.shared.global [%0], [%1], 16, %2;\n"
                 :: "r"(saddr), "l"(g), "r"(sz));
}
template <int N>
__device__ __forceinline__ void cp_wait() {
    asm volatile("cp.async.wait_group %0;\n" :: "n"(N) : "memory");
}
__device__ __forceinline__ void cp_commit() {
    asm volatile("cp.async.commit_group;\n" ::: "memory");
}

__device__ __forceinline__ void ldm4(uint32_t* r, uint32_t addr) {
    asm volatile("ldmatrix.sync.aligned.m8n8.x4.shared.b16 {%0,%1,%2,%3}, [%4];"
                 : "=r"(r[0]), "=r"(r[1]), "=r"(r[2]), "=r"(r[3]) : "r"(addr));
}

__device__ __forceinline__ void mma16816(float* d, const uint32_t* a, const uint32_t* b) {
    asm volatile(
        "mma.sync.aligned.m16n8k16.row.col.f32.bf16.bf16.f32 "
        "{%0,%1,%2,%3}, {%4,%5,%6,%7}, {%8,%9}, {%0,%1,%2,%3};"
        : "+f"(d[0]), "+f"(d[1]), "+f"(d[2]), "+f"(d[3])
        : "r"(a[0]), "r"(a[1]), "r"(a[2]), "r"(a[3]), "r"(b[0]), "r"(b[1]));
}

// ---------------- weight prep: k = 8*i + j interleaved layout ----------------
__global__ void prep_weff(const float* __restrict__ bw, const float* __restrict__ sw,
                          const float* __restrict__ ss, bf16* __restrict__ Wh,
                          bf16* __restrict__ Wl)
{
    int t = blockIdx.x * blockDim.x + threadIdx.x;
    if (t >= OUT_DIM * K_TOTAL) return;
    int o = t / K_TOTAL;
    int k = t - o * K_TOTAL;
    int i = k >> 3;
    int j = k & 7;
    float v;
    if (j == 0) v = bw[o * IN_DIM + i];
    else        v = sw[((size_t)o * IN_DIM + i) * 7 + (j - 1)] * ss[o * IN_DIM + i];
    bf16 h = __float2bfloat16(v);
    Wh[t] = h;
    Wl[t] = __float2bfloat16(v - __bfloat162float(h));
}

__global__ void cvt_split(const float* __restrict__ src, bf16* __restrict__ hi,
                          bf16* __restrict__ lo, size_t n)
{
    size_t t = (size_t)blockIdx.x * blockDim.x + threadIdx.x;
    if (t >= n) return;
    float v = src[t];
    bf16 h = __float2bfloat16(v);
    hi[t] = h;
    lo[t] = __float2bfloat16(v - __bfloat162float(h));
}

// ============== generic split-bf16 NT GEMM (ctx projection only) =============
#define TILE_BYTES 16384
#define OFF_AH 0
#define OFF_AL (TILE_BYTES)
#define OFF_BH (2 * TILE_BYTES)
#define OFF_BL (3 * TILE_BYTES)
#define STAGE_BYTES (4 * TILE_BYTES)
#define NSTAGE 3
#define SMEM_G (NSTAGE * STAGE_BYTES)

__global__ void __launch_bounds__(256, 1)
mma_gemm(const bf16* __restrict__ Ah, const bf16* __restrict__ Al,
         const bf16* __restrict__ Bh, const bf16* __restrict__ Bl,
         const float* __restrict__ bias, float* __restrict__ C,
         int M, int N, int K)
{
    extern __shared__ char smem[];
    const uint32_t sbase = smem_u32(smem);
    const int tid = threadIdx.x;
    const int wid = tid >> 5;
    const int lid = tid & 31;
    const int m0 = blockIdx.y * 128;
    const int n0 = blockIdx.x * 128;
    const int warp_m = (wid >> 2) * 64;
    const int warp_n = (wid & 3) * 32;

    float acc[4][4][4];
#pragma unroll
    for (int i = 0; i < 4; ++i)
#pragma unroll
        for (int j = 0; j < 4; ++j)
#pragma unroll
            for (int q = 0; q < 4; ++q) acc[i][j][q] = 0.f;

    auto load_stage = [&](int t, int buf) {
        const uint32_t bb = sbase + buf * STAGE_BYTES;
        const int k0 = t * 64;
        for (int i = tid; i < 1024; i += 256) {
            int row = i >> 3, c = i & 7;
            int m = m0 + row;
            uint32_t v = (m < M) ? 16u : 0u;
            size_t go = (size_t)(m < M ? m : 0) * K + k0 + c * 8;
            uint32_t so = SWZ(row * 128 + c * 16);
            cp16(bb + OFF_AH + so, Ah + go, v);
            cp16(bb + OFF_AL + so, Al + go, v);
        }
        for (int i = tid; i < 1024; i += 256) {
            int row = i >> 3, c = i & 7;
            size_t go = (size_t)(n0 + row) * K + k0 + c * 8;
            uint32_t so = SWZ(row * 128 + c * 16);
            cp16(bb + OFF_BH + so, Bh + go, 16u);
            cp16(bb + OFF_BL + so, Bl + go, 16u);
        }
        cp_commit();
    };

    const int nk = K / 64;
    load_stage(0, 0);
    if (nk > 1) load_stage(1, 1);

    for (int t = 0; t < nk; ++t) {
        __syncthreads();
        if (t + 2 < nk) load_stage(t + 2, (t + 2) % NSTAGE);
        int rem = nk - t - 1;
        if (rem >= 2)      cp_wait<2>();
        else if (rem == 1) cp_wait<1>();
        else               cp_wait<0>();
        __syncthreads();

        const uint32_t bb = sbase + (t % NSTAGE) * STAGE_BYTES;
#pragma unroll
        for (int ks = 0; ks < 4; ++ks) {
            uint32_t ah[4][4], al[4][4], bh[4][2], bl[4][2];
            {
                uint32_t row_in = ((lid >> 3) & 1) * 8 + (lid & 7);
                uint32_t kb = ks * 32 + (lid >> 4) * 16;
#pragma unroll
                for (int mf = 0; mf < 4; ++mf) {
                    uint32_t off = SWZ((warp_m + mf * 16 + row_in) * 128 + kb);
                    ldm4(ah[mf], bb + OFF_AH + off);
                    ldm4(al[mf], bb + OFF_AL + off);
                }
            }
            {
                uint32_t row_in = ((lid >> 4) & 1) * 8 + (lid & 7);
                uint32_t kb = ks * 32 + ((lid >> 3) & 1) * 16;
#pragma unroll
                for (int p = 0; p < 2; ++p) {
                    uint32_t off = SWZ((warp_n + p * 16 + row_in) * 128 + kb);
                    uint32_t r[4];
                    ldm4(r, bb + OFF_BH + off);
                    bh[2 * p][0] = r[0]; bh[2 * p][1] = r[1];
                    bh[2 * p + 1][0] = r[2]; bh[2 * p + 1][1] = r[3];
                    ldm4(r, bb + OFF_BL + off);
                    bl[2 * p][0] = r[0]; bl[2 * p][1] = r[1];
                    bl[2 * p + 1][0] = r[2]; bl[2 * p + 1][1] = r[3];
                }
            }
#pragma unroll
            for (int mf = 0; mf < 4; ++mf)
#pragma unroll
                for (int nf = 0; nf < 4; ++nf)
                    mma16816(acc[mf][nf], ah[mf], bh[nf]);
#pragma unroll
            for (int mf = 0; mf < 4; ++mf)
#pragma unroll
                for (int nf = 0; nf < 4; ++nf)
                    mma16816(acc[mf][nf], ah[mf], bl[nf]);
#pragma unroll
            for (int mf = 0; mf < 4; ++mf)
#pragma unroll
                for (int nf = 0; nf < 4; ++nf)
                    mma16816(acc[mf][nf], al[mf], bh[nf]);
        }
    }

#pragma unroll
    for (int mf = 0; mf < 4; ++mf) {
        int r0 = m0 + warp_m + mf * 16 + (lid >> 2);
#pragma unroll
        for (int nf = 0; nf < 4; ++nf) {
            int col = n0 + warp_n + nf * 8 + (lid & 3) * 2;
            float b0 = 0.f, b1 = 0.f;
            if (bias) { b0 = bias[col]; b1 = bias[col + 1]; }
            if (r0 < M) {
                float2 v = make_float2(acc[mf][nf][0] + b0, acc[mf][nf][1] + b1);
                *reinterpret_cast<float2*>(&C[(size_t)r0 * N + col]) = v;
            }
            if (r0 + 8 < M) {
                float2 v = make_float2(acc[mf][nf][2] + b0, acc[mf][nf][3] + b1);
                *reinterpret_cast<float2*>(&C[(size_t)(r0 + 8) * N + col]) = v;
            }
        }
    }
}

// ============== fused act-gen + split-bf16 GEMM (main) =======================
// out[M,256] = act(x) @ Weff^T, act computed on the fly per K-chunk.
// A buffers: 2 x (AH 16K + AL 16K) = 64 KB; B: 3 stages x 32 KB = 96 KB.
#define FA(buf) ((buf) * 32768)             // +0: AH, +16384: AL
#define FB(s)   (65536 + (s) * 32768)       // +0: BH, +16384: BL
#define SMEM_F  (65536 + 3 * 32768)         // 160 KB

__global__ void __launch_bounds__(256, 1)
fused_gemm(const float* __restrict__ node, const float* __restrict__ xc,
           const int* __restrict__ pairs, const float* __restrict__ gridp,
           const bf16* __restrict__ Wh, const bf16* __restrict__ Wl,
           float* __restrict__ C, int M)
{
    extern __shared__ char smem[];
    const uint32_t sbase = smem_u32(smem);
    const int tid = threadIdx.x;
    const int wid = tid >> 5;
    const int lid = tid & 31;
    const int m0 = blockIdx.y * 128;
    const int n0 = blockIdx.x * 128;
    const int warp_m = (wid >> 2) * 64;
    const int warp_n = (wid & 3) * 32;
    const int nk = K_TOTAL / 64;   // 48

    // uniform-grid constants
    const float g0 = gridp[0];
    const float rh = 1.f / (gridp[1] - g0);

    // per-thread x row: 2 threads per row, each owns 4 consecutive i
    const int row = tid >> 1;
    const int half = tid & 1;
    int edge = m0 + row;
    if (edge >= M) edge = 0;
    const int p0 = pairs[2 * edge];
    const int p1 = pairs[2 * edge + 1];
    const float* np0 = node + (size_t)p0 * NODE_DIM;
    const float* np1 = node + (size_t)p1 * NODE_DIM;
    const float* xcp = xc + (size_t)edge * NODE_DIM;

    auto load_x = [&](int t) -> float4 {
        int i0 = t * 8;
        const float* bp = (i0 < 128) ? np0 : (i0 < 256 ? np1 : xcp);
        return *reinterpret_cast<const float4*>(bp + (i0 & 127) + (half << 2));
    };

    // compute silu + cardinal cubic B-spline weights, store bf16 hi/lo tile
    auto compute_store = [&](float4 xv, int buf) {
        float xs[4] = {xv.x, xv.y, xv.z, xv.w};
        char* ab = smem + FA(buf);
        const int rowbase = row * 128 + (half << 6);
#pragma unroll
        for (int q = 0; q < 4; ++q) {
            float x = xs[q];
            float v[8];
            v[0] = x / (1.f + __expf(-x));               // silu
            float d = (x - g0) * rh;
            float fj = floorf(d);
            int js = (int)fj;
            float u = d - fj;
            bool inr = (d >= 0.f) && (js <= 9);
            float u2 = u * u, u3 = u2 * u;
            float om = 1.f - u;
            float c0 = om * om * om * (1.f / 6.f);
            float c1 = (3.f * u3 - 6.f * u2 + 4.f) * (1.f / 6.f);
            float c2 = (-3.f * u3 + 3.f * u2 + 3.f * u + 1.f) * (1.f / 6.f);
            float c3 = u3 * (1.f / 6.f);
#pragma unroll
            for (int j = 0; j < 7; ++j) {
                int r = j - js + 3;
                float w = 0.f;
                w = (r == 0) ? c0 : w;
                w = (r == 1) ? c1 : w;
                w = (r == 2) ? c2 : w;
                w = (r == 3) ? c3 : w;
                v[1 + j] = inr ? w : 0.f;
            }
            uint32_t hp[4], lp[4];
#pragma unroll
            for (int p = 0; p < 4; ++p) {
                float a = v[2 * p], b = v[2 * p + 1];
                __nv_bfloat162 h2 = __floats2bfloat162_rn(a, b);
                hp[p] = *reinterpret_cast<uint32_t*>(&h2);
                float ra = a - __bfloat162float(h2.x);
                float rb = b - __bfloat162float(h2.y);
                __nv_bfloat162 l2 = __floats2bfloat162_rn(ra, rb);
                lp[p] = *reinterpret_cast<uint32_t*>(&l2);
            }
            uint32_t so = SWZ((uint32_t)(rowbase + q * 16));
            *reinterpret_cast<uint4*>(ab + so) =
                make_uint4(hp[0], hp[1], hp[2], hp[3]);
            *reinterpret_cast<uint4*>(ab + 16384 + so) =
                make_uint4(lp[0], lp[1], lp[2], lp[3]);
        }
    };

    auto cp_B = [&](int t, int s) {
        const uint32_t bb = sbase + FB(s);
        const int k0 = t * 64;
        for (int i = tid; i < 1024; i += 256) {
            int r = i >> 3, c = i & 7;
            size_t go = (size_t)(n0 + r) * K_TOTAL + k0 + c * 8;
            uint32_t so = SWZ(r * 128 + c * 16);
            cp16(bb + so, Wh + go, 16u);
            cp16(bb + 16384 + so, Wl + go, 16u);
        }
        cp_commit();
    };

    float acc[4][4][4];
#pragma unroll
    for (int i = 0; i < 4; ++i)
#pragma unroll
        for (int j = 0; j < 4; ++j)
#pragma unroll
            for (int q = 0; q < 4; ++q) acc[i][j][q] = 0.f;

    // prologue
    float4 xv = load_x(0);
    cp_B(0, 0);
    cp_B(1, 1);
    compute_store(xv, 0);
    xv = load_x(1);

    for (int t = 0; t < nk; ++t) {
        if (t < nk - 1) cp_wait<1>(); else cp_wait<0>();
        __syncthreads();   // B(t) + act(t) visible; all prior readers done

        // MMA on chunk t
        {
            const uint32_t ab = sbase + FA(t & 1);
            const uint32_t bb = sbase + FB(t % 3);
#pragma unroll
            for (int ks = 0; ks < 4; ++ks) {
                uint32_t ah[4][4], al[4][4], bh[4][2], bl[4][2];
                {
                    uint32_t row_in = ((lid >> 3) & 1) * 8 + (lid & 7);
                    uint32_t kb = ks * 32 + (lid >> 4) * 16;
#pragma unroll
                    for (int mf = 0; mf < 4; ++mf) {
                        uint32_t off = SWZ((warp_m + mf * 16 + row_in) * 128 + kb);
                        ldm4(ah[mf], ab + off);
                        ldm4(al[mf], ab + 16384 + off);
                    }
                }
                {
                    uint32_t row_in = ((lid >> 4) & 1) * 8 + (lid & 7);
                    uint32_t kb = ks * 32 + ((lid >> 3) & 1) * 16;
#pragma unroll
                    for (int p = 0; p < 2; ++p) {
                        uint32_t off = SWZ((warp_n + p * 16 + row_in) * 128 + kb);
                        uint32_t r[4];
                        ldm4(r, bb + off);
                        bh[2 * p][0] = r[0]; bh[2 * p][1] = r[1];
                        bh[2 * p + 1][0] = r[2]; bh[2 * p + 1][1] = r[3];
                        ldm4(r, bb + 16384 + off);
                        bl[2 * p][0] = r[0]; bl[2 * p][1] = r[1];
                        bl[2 * p + 1][0] = r[2]; bl[2 * p + 1][1] = r[3];
                    }
                }
#pragma unroll
                for (int mf = 0; mf < 4; ++mf)
#pragma unroll
                    for (int nf = 0; nf < 4; ++nf)
                        mma16816(acc[mf][nf], ah[mf], bh[nf]);
#pragma unroll
                for (int mf = 0; mf < 4; ++mf)
#pragma unroll
                    for (int nf = 0; nf < 4; ++nf)
                        mma16816(acc[mf][nf], ah[mf], bl[nf]);
#pragma unroll
                for (int mf = 0; mf < 4; ++mf)
#pragma unroll
                    for (int nf = 0; nf < 4; ++nf)
                        mma16816(acc[mf][nf], al[mf], bh[nf]);
            }
        }

        if (t + 2 < nk) cp_B(t + 2, (t + 2) % 3);
        if (t + 1 < nk) {
            compute_store(xv, (t + 1) & 1);
            if (t + 2 < nk) xv = load_x(t + 2);
        }
    }

    // epilogue (N = 256)
#pragma unroll
    for (int mf = 0; mf < 4; ++mf) {
        int r0 = m0 + warp_m + mf * 16 + (lid >> 2);
#pragma unroll
        for (int nf = 0; nf < 4; ++nf) {
            int col = n0 + warp_n + nf * 8 + (lid & 3) * 2;
            if (r0 < M) {
                float2 v = make_float2(acc[mf][nf][0], acc[mf][nf][1]);
                *reinterpret_cast<float2*>(&C[(size_t)r0 * OUT_DIM + col]) = v;
            }
            if (r0 + 8 < M) {
                float2 v = make_float2(acc[mf][nf][2], acc[mf][nf][3]);
                *reinterpret_cast<float2*>(&C[(size_t)(r0 + 8) * OUT_DIM + col]) = v;
            }
        }
    }
}

// ---------------------------------------------------------------------------
extern "C" void kernel_launch(void* const* d_in, const int* in_sizes, int n_in,
                              void* d_out, int out_size)
{
    const float* node  = (const float*)d_in[0];
    const float* cemb  = (const float*)d_in[1];
    const int*   pairs = (const int*)  d_in[2];
    const float* ctxw  = (const float*)d_in[3];
    const float* ctxb  = (const float*)d_in[4];
    const float* bw    = (const float*)d_in[5];
    const float* sw    = (const float*)d_in[6];
    const float* ss    = (const float*)d_in[7];
    const float* grid  = (const float*)d_in[8];
    float* out = (float*)d_out;

    int nEdges = in_sizes[2] / 2;

    float *xc;
    bf16 *wh, *wl, *ceh, *cel, *cwh, *cwl;
    cudaGetSymbolAddress((void**)&xc, g_xc);
    cudaGetSymbolAddress((void**)&wh, g_w_hi);
    cudaGetSymbolAddress((void**)&wl, g_w_lo);
    cudaGetSymbolAddress((void**)&ceh, g_cemb_hi);
    cudaGetSymbolAddress((void**)&cel, g_cemb_lo);
    cudaGetSymbolAddress((void**)&cwh, g_cw_hi);
    cudaGetSymbolAddress((void**)&cwl, g_cw_lo);

    cudaFuncSetAttribute(mma_gemm, cudaFuncAttributeMaxDynamicSharedMemorySize, SMEM_G);
    cudaFuncSetAttribute(fused_gemm, cudaFuncAttributeMaxDynamicSharedMemorySize, SMEM_F);

    {
        int total = OUT_DIM * K_TOTAL;
        prep_weff<<<(total + 255) / 256, 256>>>(bw, sw, ss, wh, wl);
    }
    {
        size_t n = (size_t)NODE_DIM * CTX_DIM;
        cvt_split<<<(int)((n + 255) / 256), 256>>>(ctxw, cwh, cwl, n);
    }
    {
        size_t n = (size_t)nEdges * CTX_DIM;
        cvt_split<<<(int)((n + 255) / 256), 256>>>(cemb, ceh, cel, n);
    }

    // ctx projection  xc = cemb @ ctxw^T + b  (M=nEdges, N=128, K=256)
    {
        dim3 g(1, (nEdges + 127) / 128);
        mma_gemm<<<g, 256, SMEM_G>>>(ceh, cel, cwh, cwl, ctxb, xc,
                                     nEdges, NODE_DIM, CTX_DIM);
    }

    // fused main GEMM  out = act(x) @ weff^T  (M=nEdges, N=256, K=3072)
    {
        dim3 g(OUT_DIM / 128, (nEdges + 127) / 128);
        fused_gemm<<<g, 256, SMEM_F>>>(node, xc, pairs, grid, wh, wl, out, nEdges);
    }
}

// round 6
// speedup vs baseline: 1.3120x; 1.3120x over previous
#include <cuda_runtime.h>
#include <cuda_bf16.h>
#include <cstdint>

// ---------------- problem constants ----------------
#define NODE_DIM 128
#define CTX_DIM  256
#define OUT_DIM  256
#define IN_DIM   384
#define N_COEF   7
#define K_TOTAL  3072
#define MAX_EDGES 100000

typedef __nv_bfloat16 bf16;

// ---------------- device scratch (static) ----------------
__device__ float g_xc[(size_t)MAX_EDGES * NODE_DIM];
__device__ bf16  g_act_hi[(size_t)MAX_EDGES * K_TOTAL];
__device__ bf16  g_act_lo[(size_t)MAX_EDGES * K_TOTAL];
__device__ bf16  g_w_hi[(size_t)OUT_DIM * K_TOTAL];
__device__ bf16  g_w_lo[(size_t)OUT_DIM * K_TOTAL];
__device__ bf16  g_cemb_hi[(size_t)MAX_EDGES * CTX_DIM];
__device__ bf16  g_cemb_lo[(size_t)MAX_EDGES * CTX_DIM];
__device__ bf16  g_cw_hi[(size_t)NODE_DIM * CTX_DIM];
__device__ bf16  g_cw_lo[(size_t)NODE_DIM * CTX_DIM];

// ---------------- helpers ----------------
__device__ __forceinline__ uint32_t smem_u32(const void* p) {
    uint32_t a;
    asm("{ .reg .u64 t; cvta.to.shared.u64 t, %1; cvt.u32.u64 %0, t; }" : "=r"(a) : "l"(p));
    return a;
}
#define SWZ(x) ((x) ^ (((x) >> 3) & 0x70))

__device__ __forceinline__ void cp16(uint32_t saddr, const void* g, uint32_t sz) {
    asm volatile("cp.async.cg.shared.global [%0], [%1], 16, %2;\n"
                 :: "r"(saddr), "l"(g), "r"(sz));
}
template <int N>
__device__ __forceinline__ void cp_wait() {
    asm volatile("cp.async.wait_group %0;\n" :: "n"(N) : "memory");
}
__device__ __forceinline__ void cp_commit() {
    asm volatile("cp.async.commit_group;\n" ::: "memory");
}

__device__ __forceinline__ void ldm4(uint32_t* r, uint32_t addr) {
    asm volatile("ldmatrix.sync.aligned.m8n8.x4.shared.b16 {%0,%1,%2,%3}, [%4];"
                 : "=r"(r[0]), "=r"(r[1]), "=r"(r[2]), "=r"(r[3]) : "r"(addr));
}

__device__ __forceinline__ void mma16816(float* d, const uint32_t* a, const uint32_t* b) {
    asm volatile(
        "mma.sync.aligned.m16n8k16.row.col.f32.bf16.bf16.f32 "
        "{%0,%1,%2,%3}, {%4,%5,%6,%7}, {%8,%9}, {%0,%1,%2,%3};"
        : "+f"(d[0]), "+f"(d[1]), "+f"(d[2]), "+f"(d[3])
        : "r"(a[0]), "r"(a[1]), "r"(a[2]), "r"(a[3]), "r"(b[0]), "r"(b[1]));
}

// ---------------- weight prep (coefficient-major spline layout) ------------
__global__ void prep_weff(const float* __restrict__ bw, const float* __restrict__ sw,
                          const float* __restrict__ ss, bf16* __restrict__ Wh,
                          bf16* __restrict__ Wl)
{
    int t = blockIdx.x * blockDim.x + threadIdx.x;
    if (t >= OUT_DIM * K_TOTAL) return;
    int o = t / K_TOTAL;
    int k = t - o * K_TOTAL;
    float v;
    if (k < IN_DIM) v = bw[o * IN_DIM + k];
    else {
        int r = k - IN_DIM;
        int c = r / IN_DIM;
        int i = r - c * IN_DIM;
        v = sw[((size_t)o * IN_DIM + i) * N_COEF + c] * ss[o * IN_DIM + i];
    }
    bf16 h = __float2bfloat16(v);
    Wh[t] = h;
    Wl[t] = __float2bfloat16(v - __bfloat162float(h));
}

__global__ void cvt_split(const float* __restrict__ src, bf16* __restrict__ hi,
                          bf16* __restrict__ lo, size_t n)
{
    size_t t = (size_t)blockIdx.x * blockDim.x + threadIdx.x;
    if (t >= n) return;
    float v = src[t];
    bf16 h = __float2bfloat16(v);
    hi[t] = h;
    lo[t] = __float2bfloat16(v - __bfloat162float(h));
}

// ---------------- mma.sync split-bf16 NT GEMM, 512 threads ----------------
// C = (Ah+Al)(Bh+Bl)^T (+bias); 3 passes hh+hl+lh.
// BM=128, BN=128, BK=64; 16 warps in 4(m)x4(n); warp tile 32x32.
// 3-stage cp.async pipeline, SW128 smem.
#define TILE_BYTES 16384
#define OFF_AH 0
#define OFF_AL (TILE_BYTES)
#define OFF_BH (2 * TILE_BYTES)
#define OFF_BL (3 * TILE_BYTES)
#define STAGE_BYTES (4 * TILE_BYTES)
#define NSTAGE 3
#define SMEM_TOTAL (NSTAGE * STAGE_BYTES)   // 192 KB

__global__ void __launch_bounds__(512, 1)
mma_gemm(const bf16* __restrict__ Ah, const bf16* __restrict__ Al,
         const bf16* __restrict__ Bh, const bf16* __restrict__ Bl,
         const float* __restrict__ bias, float* __restrict__ C,
         int M, int N, int K)
{
    extern __shared__ char smem[];
    const uint32_t sbase = smem_u32(smem);
    const int tid = threadIdx.x;
    const int wid = tid >> 5;
    const int lid = tid & 31;
    const int m0 = blockIdx.y * 128;
    const int n0 = blockIdx.x * 128;

    const int warp_m = (wid >> 2) * 32;   // 4 warp-rows of 32
    const int warp_n = (wid & 3) * 32;    // 4 warp-cols of 32

    float acc[2][4][4];
#pragma unroll
    for (int i = 0; i < 2; ++i)
#pragma unroll
        for (int j = 0; j < 4; ++j)
#pragma unroll
            for (int q = 0; q < 4; ++q) acc[i][j][q] = 0.f;

    auto load_stage = [&](int t, int buf) {
        const uint32_t bb = sbase + buf * STAGE_BYTES;
        const int k0 = t * 64;
        for (int i = tid; i < 1024; i += 512) {
            int row = i >> 3, c = i & 7;
            int m = m0 + row;
            uint32_t v = (m < M) ? 16u : 0u;   // size-0 cp.async zero-fills
            size_t go = (size_t)(m < M ? m : 0) * K + k0 + c * 8;
            uint32_t so = SWZ(row * 128 + c * 16);
            cp16(bb + OFF_AH + so, Ah + go, v);
            cp16(bb + OFF_AL + so, Al + go, v);
        }
        for (int i = tid; i < 1024; i += 512) {
            int row = i >> 3, c = i & 7;
            size_t go = (size_t)(n0 + row) * K + k0 + c * 8;
            uint32_t so = SWZ(row * 128 + c * 16);
            cp16(bb + OFF_BH + so, Bh + go, 16u);
            cp16(bb + OFF_BL + so, Bl + go, 16u);
        }
        cp_commit();
    };

    const int nk = K / 64;
    load_stage(0, 0);
    if (nk > 1) load_stage(1, 1);

    for (int t = 0; t < nk; ++t) {
        __syncthreads();   // protect buffer (t+2)%3
        if (t + 2 < nk) load_stage(t + 2, (t + 2) % NSTAGE);
        int rem = nk - t - 1;
        if (rem >= 2)      cp_wait<2>();
        else if (rem == 1) cp_wait<1>();
        else               cp_wait<0>();
        __syncthreads();

        const uint32_t bb = sbase + (t % NSTAGE) * STAGE_BYTES;
#pragma unroll
        for (int ks = 0; ks < 4; ++ks) {
            uint32_t ah[2][4], al[2][4], bh[4][2], bl[4][2];
            {
                uint32_t row_in = ((lid >> 3) & 1) * 8 + (lid & 7);
                uint32_t kb = ks * 32 + (lid >> 4) * 16;
#pragma unroll
                for (int mf = 0; mf < 2; ++mf) {
                    uint32_t off = SWZ((warp_m + mf * 16 + row_in) * 128 + kb);
                    ldm4(ah[mf], bb + OFF_AH + off);
                    ldm4(al[mf], bb + OFF_AL + off);
                }
            }
            {
                uint32_t row_in = ((lid >> 4) & 1) * 8 + (lid & 7);
                uint32_t kb = ks * 32 + ((lid >> 3) & 1) * 16;
#pragma unroll
                for (int p = 0; p < 2; ++p) {
                    uint32_t off = SWZ((warp_n + p * 16 + row_in) * 128 + kb);
                    uint32_t r[4];
                    ldm4(r, bb + OFF_BH + off);
                    bh[2 * p][0] = r[0]; bh[2 * p][1] = r[1];
                    bh[2 * p + 1][0] = r[2]; bh[2 * p + 1][1] = r[3];
                    ldm4(r, bb + OFF_BL + off);
                    bl[2 * p][0] = r[0]; bl[2 * p][1] = r[1];
                    bl[2 * p + 1][0] = r[2]; bl[2 * p + 1][1] = r[3];
                }
            }
#pragma unroll
            for (int mf = 0; mf < 2; ++mf)
#pragma unroll
                for (int nf = 0; nf < 4; ++nf)
                    mma16816(acc[mf][nf], ah[mf], bh[nf]);
#pragma unroll
            for (int mf = 0; mf < 2; ++mf)
#pragma unroll
                for (int nf = 0; nf < 4; ++nf)
                    mma16816(acc[mf][nf], ah[mf], bl[nf]);
#pragma unroll
            for (int mf = 0; mf < 2; ++mf)
#pragma unroll
                for (int nf = 0; nf < 4; ++nf)
                    mma16816(acc[mf][nf], al[mf], bh[nf]);
        }
    }

    // epilogue
#pragma unroll
    for (int mf = 0; mf < 2; ++mf) {
        int r0 = m0 + warp_m + mf * 16 + (lid >> 2);
#pragma unroll
        for (int nf = 0; nf < 4; ++nf) {
            int col = n0 + warp_n + nf * 8 + (lid & 3) * 2;
            float b0 = 0.f, b1 = 0.f;
            if (bias) { b0 = bias[col]; b1 = bias[col + 1]; }
            if (r0 < M) {
                float2 v = make_float2(acc[mf][nf][0] + b0, acc[mf][nf][1] + b1);
                *reinterpret_cast<float2*>(&C[(size_t)r0 * N + col]) = v;
            }
            if (r0 + 8 < M) {
                float2 v = make_float2(acc[mf][nf][2] + b0, acc[mf][nf][3] + b1);
                *reinterpret_cast<float2*>(&C[(size_t)(r0 + 8) * N + col]) = v;
            }
        }
    }
}

// ---------------- activation builder (coefficient-major spline layout) -----
__global__ void build_act(const float* __restrict__ node, const float* __restrict__ xc,
                          const int* __restrict__ pairs, const float* __restrict__ grid,
                          bf16* __restrict__ acth, bf16* __restrict__ actl, int nEdges)
{
    __shared__ float g[11];
    __shared__ float inv[3][11];
    if (threadIdx.x < 11) g[threadIdx.x] = grid[threadIdx.x];  // grid rows identical
    __syncthreads();
    if (threadIdx.x < 11) {
        int j = threadIdx.x;
#pragma unroll
        for (int k = 1; k <= 3; ++k)
            if (j <= 10 - k) inv[k - 1][j] = 1.f / (g[j + k] - g[j]);
    }
    __syncthreads();

    int t = blockIdx.x * blockDim.x + threadIdx.x;
    if (t >= nEdges * IN_DIM) return;
    int n = t / IN_DIM;
    int i = t - n * IN_DIM;

    float x;
    if (i < NODE_DIM) {
        int p = pairs[2 * n];
        x = node[(size_t)p * NODE_DIM + i];
    } else if (i < 2 * NODE_DIM) {
        int p = pairs[2 * n + 1];
        x = node[(size_t)p * NODE_DIM + (i - NODE_DIM)];
    } else {
        x = xc[(size_t)n * NODE_DIM + (i - 2 * NODE_DIM)];
    }

    float s = x / (1.f + expf(-x));

    float b[10];
#pragma unroll
    for (int j = 0; j < 10; ++j) b[j] = (x >= g[j] && x < g[j + 1]) ? 1.f : 0.f;
#pragma unroll
    for (int k = 1; k <= 3; ++k) {
#pragma unroll
        for (int j = 0; j < 10; ++j) {
            if (j < 10 - k) {
                b[j] = (x - g[j]) * inv[k - 1][j] * b[j]
                     + (g[j + k + 1] - x) * inv[k - 1][j + 1] * b[j + 1];
            }
        }
    }

    size_t base = (size_t)n * K_TOTAL;
    {
        bf16 h = __float2bfloat16(s);
        acth[base + i] = h;
        actl[base + i] = __float2bfloat16(s - __bfloat162float(h));
    }
#pragma unroll
    for (int c = 0; c < N_COEF; ++c) {
        size_t idx = base + IN_DIM + (size_t)c * IN_DIM + i;   // coalesced over i
        bf16 h = __float2bfloat16(b[c]);
        acth[idx] = h;
        actl[idx] = __float2bfloat16(b[c] - __bfloat162float(h));
    }
}

// ---------------------------------------------------------------------------
extern "C" void kernel_launch(void* const* d_in, const int* in_sizes, int n_in,
                              void* d_out, int out_size)
{
    const float* node  = (const float*)d_in[0];
    const float* cemb  = (const float*)d_in[1];
    const int*   pairs = (const int*)  d_in[2];
    const float* ctxw  = (const float*)d_in[3];
    const float* ctxb  = (const float*)d_in[4];
    const float* bw    = (const float*)d_in[5];
    const float* sw    = (const float*)d_in[6];
    const float* ss    = (const float*)d_in[7];
    const float* grid  = (const float*)d_in[8];
    float* out = (float*)d_out;

    int nEdges = in_sizes[2] / 2;

    float *xc;
    bf16 *acth, *actl, *wh, *wl, *ceh, *cel, *cwh, *cwl;
    cudaGetSymbolAddress((void**)&xc, g_xc);
    cudaGetSymbolAddress((void**)&acth, g_act_hi);
    cudaGetSymbolAddress((void**)&actl, g_act_lo);
    cudaGetSymbolAddress((void**)&wh, g_w_hi);
    cudaGetSymbolAddress((void**)&wl, g_w_lo);
    cudaGetSymbolAddress((void**)&ceh, g_cemb_hi);
    cudaGetSymbolAddress((void**)&cel, g_cemb_lo);
    cudaGetSymbolAddress((void**)&cwh, g_cw_hi);
    cudaGetSymbolAddress((void**)&cwl, g_cw_lo);

    cudaFuncSetAttribute(mma_gemm, cudaFuncAttributeMaxDynamicSharedMemorySize, SMEM_TOTAL);

    {
        int total = OUT_DIM * K_TOTAL;
        prep_weff<<<(total + 255) / 256, 256>>>(bw, sw, ss, wh, wl);
    }
    {
        size_t n = (size_t)NODE_DIM * CTX_DIM;
        cvt_split<<<(int)((n + 255) / 256), 256>>>(ctxw, cwh, cwl, n);
    }
    {
        size_t n = (size_t)nEdges * CTX_DIM;
        cvt_split<<<(int)((n + 255) / 256), 256>>>(cemb, ceh, cel, n);
    }

    // ctx projection  xc = cemb @ ctxw^T + b  (M=nEdges, N=128, K=256)
    {
        dim3 g(1, (nEdges + 127) / 128);
        mma_gemm<<<g, 512, SMEM_TOTAL>>>(ceh, cel, cwh, cwl, ctxb, xc,
                                         nEdges, NODE_DIM, CTX_DIM);
    }

    // activations
    {
        int total = nEdges * IN_DIM;
        build_act<<<(total + 255) / 256, 256>>>(node, xc, pairs, grid, acth, actl, nEdges);
    }

    // main GEMM  out = act @ weff^T  (M=nEdges, N=256, K=3072)
    {
        dim3 g(OUT_DIM / 128, (nEdges + 127) / 128);
        mma_gemm<<<g, 512, SMEM_TOTAL>>>(acth, actl, wh, wl, nullptr, out,
                                         nEdges, OUT_DIM, K_TOTAL);
    }
}

// round 8
// speedup vs baseline: 1.6373x; 1.2480x over previous
#include <cuda_runtime.h>
#include <cuda_bf16.h>
#include <cuda_fp16.h>
#include <cstdint>

// ---------------- problem constants ----------------
#define NODE_DIM 128
#define CTX_DIM  256
#define OUT_DIM  256
#define IN_DIM   384
#define N_COEF   7
#define K_TOTAL  3072        // coefficient-major: k<384 silu, k>=384: c*384+i
#define MAX_EDGES 100000

typedef __nv_bfloat16 bf16;

// ---------------- device scratch (static) ----------------
__device__ float g_xc[(size_t)MAX_EDGES * NODE_DIM];
__device__ half  g_act_h[(size_t)MAX_EDGES * K_TOTAL];    // 614 MB
__device__ half  g_act_l[(size_t)MAX_EDGES * IN_DIM];     // 77 MB (silu lo only)
__device__ half  g_w_h[(size_t)OUT_DIM * K_TOTAL];
__device__ half  g_w_l[(size_t)OUT_DIM * K_TOTAL];
__device__ bf16  g_cemb_hi[(size_t)MAX_EDGES * CTX_DIM];
__device__ bf16  g_cemb_lo[(size_t)MAX_EDGES * CTX_DIM];
__device__ bf16  g_cw_hi[(size_t)NODE_DIM * CTX_DIM];
__device__ bf16  g_cw_lo[(size_t)NODE_DIM * CTX_DIM];

// ---------------- helpers ----------------
__device__ __forceinline__ uint32_t smem_u32(const void* p) {
    uint32_t a;
    asm("{ .reg .u64 t; cvta.to.shared.u64 t, %1; cvt.u32.u64 %0, t; }" : "=r"(a) : "l"(p));
    return a;
}
#define SWZ(x) ((x) ^ (((x) >> 3) & 0x70))

__device__ __forceinline__ void cp16(uint32_t saddr, const void* g, uint32_t sz) {
    asm volatile("cp.async.cg.shared.global [%0], [%1], 16, %2;\n"
                 :: "r"(saddr), "l"(g), "r"(sz));
}
template <int N>
__device__ __forceinline__ void cp_wait() {
    asm volatile("cp.async.wait_group %0;\n" :: "n"(N) : "memory");
}
__device__ __forceinline__ void cp_commit() {
    asm volatile("cp.async.commit_group;\n" ::: "memory");
}

__device__ __forceinline__ void ldm4(uint32_t* r, uint32_t addr) {
    asm volatile("ldmatrix.sync.aligned.m8n8.x4.shared.b16 {%0,%1,%2,%3}, [%4];"
                 : "=r"(r[0]), "=r"(r[1]), "=r"(r[2]), "=r"(r[3]) : "r"(addr));
}

__device__ __forceinline__ void mma_bf16(float* d, const uint32_t* a, const uint32_t* b) {
    asm volatile(
        "mma.sync.aligned.m16n8k16.row.col.f32.bf16.bf16.f32 "
        "{%0,%1,%2,%3}, {%4,%5,%6,%7}, {%8,%9}, {%0,%1,%2,%3};"
        : "+f"(d[0]), "+f"(d[1]), "+f"(d[2]), "+f"(d[3])
        : "r"(a[0]), "r"(a[1]), "r"(a[2]), "r"(a[3]), "r"(b[0]), "r"(b[1]));
}
__device__ __forceinline__ void mma_f16(float* d, const uint32_t* a, const uint32_t* b) {
    asm volatile(
        "mma.sync.aligned.m16n8k16.row.col.f32.f16.f16.f32 "
        "{%0,%1,%2,%3}, {%4,%5,%6,%7}, {%8,%9}, {%0,%1,%2,%3};"
        : "+f"(d[0]), "+f"(d[1]), "+f"(d[2]), "+f"(d[3])
        : "r"(a[0]), "r"(a[1]), "r"(a[2]), "r"(a[3]), "r"(b[0]), "r"(b[1]));
}

// ---------------- weight prep: fp16 hi/lo, coefficient-major ---------------
__global__ void prep_weff(const float* __restrict__ bw, const float* __restrict__ sw,
                          const float* __restrict__ ss, half* __restrict__ Wh,
                          half* __restrict__ Wl)
{
    int t = blockIdx.x * blockDim.x + threadIdx.x;
    if (t >= OUT_DIM * K_TOTAL) return;
    int o = t / K_TOTAL;
    int k = t - o * K_TOTAL;
    float v;
    if (k < IN_DIM) v = bw[o * IN_DIM + k];
    else {
        int r = k - IN_DIM;
        int c = r / IN_DIM;
        int i = r - c * IN_DIM;
        v = sw[((size_t)o * IN_DIM + i) * N_COEF + c] * ss[o * IN_DIM + i];
    }
    half h = __float2half_rn(v);
    Wh[t] = h;
    Wl[t] = __float2half_rn(v - __half2float(h));
}

__global__ void cvt_split(const float* __restrict__ src, bf16* __restrict__ hi,
                          bf16* __restrict__ lo, size_t n)
{
    size_t t = (size_t)blockIdx.x * blockDim.x + threadIdx.x;
    if (t >= n) return;
    float v = src[t];
    bf16 h = __float2bfloat16(v);
    hi[t] = h;
    lo[t] = __float2bfloat16(v - __bfloat162float(h));
}

// ============ ctx GEMM: bf16 split 3-pass (proven R4 code, 256thr) ==========
#define TILE_BYTES 16384
#define OFF_AH 0
#define OFF_AL (TILE_BYTES)
#define OFF_BH (2 * TILE_BYTES)
#define OFF_BL (3 * TILE_BYTES)
#define STAGE_BYTES (4 * TILE_BYTES)
#define NSTAGE 3
#define SMEM_CTX (NSTAGE * STAGE_BYTES)

__global__ void __launch_bounds__(256, 1)
ctx_gemm(const bf16* __restrict__ Ah, const bf16* __restrict__ Al,
         const bf16* __restrict__ Bh, const bf16* __restrict__ Bl,
         const float* __restrict__ bias, float* __restrict__ C,
         int M, int N, int K)
{
    extern __shared__ char smem[];
    const uint32_t sbase = smem_u32(smem);
    const int tid = threadIdx.x;
    const int wid = tid >> 5;
    const int lid = tid & 31;
    const int m0 = blockIdx.y * 128;
    const int n0 = blockIdx.x * 128;
    const int warp_m = (wid >> 2) * 64;
    const int warp_n = (wid & 3) * 32;

    float acc[4][4][4];
#pragma unroll
    for (int i = 0; i < 4; ++i)
#pragma unroll
        for (int j = 0; j < 4; ++j)
#pragma unroll
            for (int q = 0; q < 4; ++q) acc[i][j][q] = 0.f;

    auto load_stage = [&](int t, int buf) {
        const uint32_t bb = sbase + buf * STAGE_BYTES;
        const int k0 = t * 64;
        for (int i = tid; i < 1024; i += 256) {
            int row = i >> 3, c = i & 7;
            int m = m0 + row;
            uint32_t v = (m < M) ? 16u : 0u;
            size_t go = (size_t)(m < M ? m : 0) * K + k0 + c * 8;
            uint32_t so = SWZ(row * 128 + c * 16);
            cp16(bb + OFF_AH + so, Ah + go, v);
            cp16(bb + OFF_AL + so, Al + go, v);
        }
        for (int i = tid; i < 1024; i += 256) {
            int row = i >> 3, c = i & 7;
            size_t go = (size_t)(n0 + row) * K + k0 + c * 8;
            uint32_t so = SWZ(row * 128 + c * 16);
            cp16(bb + OFF_BH + so, Bh + go, 16u);
            cp16(bb + OFF_BL + so, Bl + go, 16u);
        }
        cp_commit();
    };

    const int nk = K / 64;
    load_stage(0, 0);
    if (nk > 1) load_stage(1, 1);

    for (int t = 0; t < nk; ++t) {
        if (t < nk - 1) cp_wait<1>(); else cp_wait<0>();
        __syncthreads();
        if (t + 2 < nk) load_stage(t + 2, (t + 2) % NSTAGE);

        const uint32_t bb = sbase + (t % NSTAGE) * STAGE_BYTES;
#pragma unroll
        for (int ks = 0; ks < 4; ++ks) {
            uint32_t ah[4][4], al[4][4], bh[4][2], bl[4][2];
            {
                uint32_t row_in = ((lid >> 3) & 1) * 8 + (lid & 7);
                uint32_t kb = ks * 32 + (lid >> 4) * 16;
#pragma unroll
                for (int mf = 0; mf < 4; ++mf) {
                    uint32_t off = SWZ((warp_m + mf * 16 + row_in) * 128 + kb);
                    ldm4(ah[mf], bb + OFF_AH + off);
                    ldm4(al[mf], bb + OFF_AL + off);
                }
            }
            {
                uint32_t row_in = ((lid >> 4) & 1) * 8 + (lid & 7);
                uint32_t kb = ks * 32 + ((lid >> 3) & 1) * 16;
#pragma unroll
                for (int p = 0; p < 2; ++p) {
                    uint32_t off = SWZ((warp_n + p * 16 + row_in) * 128 + kb);
                    uint32_t r[4];
                    ldm4(r, bb + OFF_BH + off);
                    bh[2 * p][0] = r[0]; bh[2 * p][1] = r[1];
                    bh[2 * p + 1][0] = r[2]; bh[2 * p + 1][1] = r[3];
                    ldm4(r, bb + OFF_BL + off);
                    bl[2 * p][0] = r[0]; bl[2 * p][1] = r[1];
                    bl[2 * p + 1][0] = r[2]; bl[2 * p + 1][1] = r[3];
                }
            }
#pragma unroll
            for (int mf = 0; mf < 4; ++mf)
#pragma unroll
                for (int nf = 0; nf < 4; ++nf)
                    mma_bf16(acc[mf][nf], ah[mf], bh[nf]);
#pragma unroll
            for (int mf = 0; mf < 4; ++mf)
#pragma unroll
                for (int nf = 0; nf < 4; ++nf)
                    mma_bf16(acc[mf][nf], ah[mf], bl[nf]);
#pragma unroll
            for (int mf = 0; mf < 4; ++mf)
#pragma unroll
                for (int nf = 0; nf < 4; ++nf)
                    mma_bf16(acc[mf][nf], al[mf], bh[nf]);
        }
        __syncthreads();
    }

#pragma unroll
    for (int mf = 0; mf < 4; ++mf) {
        int r0 = m0 + warp_m + mf * 16 + (lid >> 2);
#pragma unroll
        for (int nf = 0; nf < 4; ++nf) {
            int col = n0 + warp_n + nf * 8 + (lid & 3) * 2;
            float b0 = bias ? bias[col] : 0.f;
            float b1 = bias ? bias[col + 1] : 0.f;
            if (r0 < M) {
                float2 v = make_float2(acc[mf][nf][0] + b0, acc[mf][nf][1] + b1);
                *reinterpret_cast<float2*>(&C[(size_t)r0 * N + col]) = v;
            }
            if (r0 + 8 < M) {
                float2 v = make_float2(acc[mf][nf][2] + b0, acc[mf][nf][3] + b1);
                *reinterpret_cast<float2*>(&C[(size_t)(r0 + 8) * N + col]) = v;
            }
        }
    }
}

// ============ main GEMM: fp16 hybrid 2.5-pass ================================
// chunks 0..5 (silu, k<384): 3 passes  Ah*Bh + Ah*Bl + Al*Bh
// chunks 6..47 (spline):     2 passes  Ah*Bh + Ah*Bl      (A single fp16)
#define MOFF_AH 0
#define MOFF_AL 16384
#define MOFF_BH 32768
#define MOFF_BL 49152
#define MSTAGE  65536
#define SMEM_MAIN (3 * 65536)     // 192 KB

__global__ void __launch_bounds__(256, 1)
main_gemm(const half* __restrict__ Ah, const half* __restrict__ Alo,
          const half* __restrict__ Bh, const half* __restrict__ Bl,
          float* __restrict__ C, int M)
{
    extern __shared__ char smem[];
    const uint32_t sbase = smem_u32(smem);
    const int tid = threadIdx.x;
    const int wid = tid >> 5;
    const int lid = tid & 31;
    const int m0 = blockIdx.y * 128;
    const int n0 = blockIdx.x * 128;
    const int warp_m = (wid >> 2) * 64;
    const int warp_n = (wid & 3) * 32;
    const int nk = K_TOTAL / 64;   // 48; silu = chunks 0..5

    float acc[4][4][4];
#pragma unroll
    for (int i = 0; i < 4; ++i)
#pragma unroll
        for (int j = 0; j < 4; ++j)
#pragma unroll
            for (int q = 0; q < 4; ++q) acc[i][j][q] = 0.f;

    auto load_stage = [&](int t, int buf) {
        const uint32_t bb = sbase + buf * MSTAGE;
        const int k0 = t * 64;
        for (int i = tid; i < 1024; i += 256) {
            int row = i >> 3, c = i & 7;
            int m = m0 + row;
            uint32_t v = (m < M) ? 16u : 0u;
            uint32_t so = SWZ(row * 128 + c * 16);
            cp16(bb + MOFF_AH + so,
                 Ah + (size_t)(m < M ? m : 0) * K_TOTAL + k0 + c * 8, v);
            if (t < 6)
                cp16(bb + MOFF_AL + so,
                     Alo + (size_t)(m < M ? m : 0) * IN_DIM + k0 + c * 8, v);
        }
        for (int i = tid; i < 1024; i += 256) {
            int row = i >> 3, c = i & 7;
            size_t go = (size_t)(n0 + row) * K_TOTAL + k0 + c * 8;
            uint32_t so = SWZ(row * 128 + c * 16);
            cp16(bb + MOFF_BH + so, Bh + go, 16u);
            cp16(bb + MOFF_BL + so, Bl + go, 16u);
        }
        cp_commit();
    };

    load_stage(0, 0);
    load_stage(1, 1);

    for (int t = 0; t < nk; ++t) {
        if (t < nk - 1) cp_wait<1>(); else cp_wait<0>();
        __syncthreads();   // stage t ready; all warps done reading stage t-1
        if (t + 2 < nk) load_stage(t + 2, (t + 2) % 3);

        const uint32_t bb = sbase + (t % 3) * MSTAGE;
        const bool silu = (t < 6);
#pragma unroll
        for (int ks = 0; ks < 4; ++ks) {
            uint32_t ah[4][4], al[4][4], bh[4][2], bl[4][2];
            {
                uint32_t row_in = ((lid >> 3) & 1) * 8 + (lid & 7);
                uint32_t kb = ks * 32 + (lid >> 4) * 16;
#pragma unroll
                for (int mf = 0; mf < 4; ++mf) {
                    uint32_t off = SWZ((warp_m + mf * 16 + row_in) * 128 + kb);
                    ldm4(ah[mf], bb + MOFF_AH + off);
                    if (silu) ldm4(al[mf], bb + MOFF_AL + off);
                }
            }
            {
                uint32_t row_in = ((lid >> 4) & 1) * 8 + (lid & 7);
                uint32_t kb = ks * 32 + ((lid >> 3) & 1) * 16;
#pragma unroll
                for (int p = 0; p < 2; ++p) {
                    uint32_t off = SWZ((warp_n + p * 16 + row_in) * 128 + kb);
                    uint32_t r[4];
                    ldm4(r, bb + MOFF_BH + off);
                    bh[2 * p][0] = r[0]; bh[2 * p][1] = r[1];
                    bh[2 * p + 1][0] = r[2]; bh[2 * p + 1][1] = r[3];
                    ldm4(r, bb + MOFF_BL + off);
                    bl[2 * p][0] = r[0]; bl[2 * p][1] = r[1];
                    bl[2 * p + 1][0] = r[2]; bl[2 * p + 1][1] = r[3];
                }
            }
#pragma unroll
            for (int mf = 0; mf < 4; ++mf)
#pragma unroll
                for (int nf = 0; nf < 4; ++nf)
                    mma_f16(acc[mf][nf], ah[mf], bh[nf]);
#pragma unroll
            for (int mf = 0; mf < 4; ++mf)
#pragma unroll
                for (int nf = 0; nf < 4; ++nf)
                    mma_f16(acc[mf][nf], ah[mf], bl[nf]);
            if (silu) {
#pragma unroll
                for (int mf = 0; mf < 4; ++mf)
#pragma unroll
                    for (int nf = 0; nf < 4; ++nf)
                        mma_f16(acc[mf][nf], al[mf], bh[nf]);
            }
        }
    }

#pragma unroll
    for (int mf = 0; mf < 4; ++mf) {
        int r0 = m0 + warp_m + mf * 16 + (lid >> 2);
#pragma unroll
        for (int nf = 0; nf < 4; ++nf) {
            int col = n0 + warp_n + nf * 8 + (lid & 3) * 2;
            if (r0 < M) {
                float2 v = make_float2(acc[mf][nf][0], acc[mf][nf][1]);
                *reinterpret_cast<float2*>(&C[(size_t)r0 * OUT_DIM + col]) = v;
            }
            if (r0 + 8 < M) {
                float2 v = make_float2(acc[mf][nf][2], acc[mf][nf][3]);
                *reinterpret_cast<float2*>(&C[(size_t)(r0 + 8) * OUT_DIM + col]) = v;
            }
        }
    }
}

// ---------------- activation builder (fp16, silu lo separate) ---------------
__global__ void build_act(const float* __restrict__ node, const float* __restrict__ xc,
                          const int* __restrict__ pairs, const float* __restrict__ grid,
                          half* __restrict__ acth, half* __restrict__ actl, int nEdges)
{
    __shared__ float g[11];
    __shared__ float inv[3][11];
    if (threadIdx.x < 11) g[threadIdx.x] = grid[threadIdx.x];  // grid rows identical
    __syncthreads();
    if (threadIdx.x < 11) {
        int j = threadIdx.x;
#pragma unroll
        for (int k = 1; k <= 3; ++k)
            if (j <= 10 - k) inv[k - 1][j] = 1.f / (g[j + k] - g[j]);
    }
    __syncthreads();

    int t = blockIdx.x * blockDim.x + threadIdx.x;
    if (t >= nEdges * IN_DIM) return;
    int n = t / IN_DIM;
    int i = t - n * IN_DIM;

    float x;
    if (i < NODE_DIM) {
        int p = pairs[2 * n];
        x = node[(size_t)p * NODE_DIM + i];
    } else if (i < 2 * NODE_DIM) {
        int p = pairs[2 * n + 1];
        x = node[(size_t)p * NODE_DIM + (i - NODE_DIM)];
    } else {
        x = xc[(size_t)n * NODE_DIM + (i - 2 * NODE_DIM)];
    }

    float s = x / (1.f + expf(-x));

    float b[10];
#pragma unroll
    for (int j = 0; j < 10; ++j) b[j] = (x >= g[j] && x < g[j + 1]) ? 1.f : 0.f;
#pragma unroll
    for (int k = 1; k <= 3; ++k) {
#pragma unroll
        for (int j = 0; j < 10; ++j) {
            if (j < 10 - k) {
                b[j] = (x - g[j]) * inv[k - 1][j] * b[j]
                     + (g[j + k + 1] - x) * inv[k - 1][j + 1] * b[j + 1];
            }
        }
    }

    size_t base = (size_t)n * K_TOTAL;
    {
        half h = __float2half_rn(s);
        acth[base + i] = h;
        actl[(size_t)n * IN_DIM + i] = __float2half_rn(s - __half2float(h));
    }
#pragma unroll
    for (int c = 0; c < N_COEF; ++c)
        acth[base + IN_DIM + (size_t)c * IN_DIM + i] = __float2half_rn(b[c]);
}

// ---------------------------------------------------------------------------
extern "C" void kernel_launch(void* const* d_in, const int* in_sizes, int n_in,
                              void* d_out, int out_size)
{
    const float* node  = (const float*)d_in[0];
    const float* cemb  = (const float*)d_in[1];
    const int*   pairs = (const int*)  d_in[2];
    const float* ctxw  = (const float*)d_in[3];
    const float* ctxb  = (const float*)d_in[4];
    const float* bw    = (const float*)d_in[5];
    const float* sw    = (const float*)d_in[6];
    const float* ss    = (const float*)d_in[7];
    const float* grid  = (const float*)d_in[8];
    float* out = (float*)d_out;

    int nEdges = in_sizes[2] / 2;

    float *xc;
    half *acth, *actl, *wh, *wl;
    bf16 *ceh, *cel, *cwh, *cwl;
    cudaGetSymbolAddress((void**)&xc, g_xc);
    cudaGetSymbolAddress((void**)&acth, g_act_h);
    cudaGetSymbolAddress((void**)&actl, g_act_l);
    cudaGetSymbolAddress((void**)&wh, g_w_h);
    cudaGetSymbolAddress((void**)&wl, g_w_l);
    cudaGetSymbolAddress((void**)&ceh, g_cemb_hi);
    cudaGetSymbolAddress((void**)&cel, g_cemb_lo);
    cudaGetSymbolAddress((void**)&cwh, g_cw_hi);
    cudaGetSymbolAddress((void**)&cwl, g_cw_lo);

    cudaFuncSetAttribute(ctx_gemm, cudaFuncAttributeMaxDynamicSharedMemorySize, SMEM_CTX);
    cudaFuncSetAttribute(main_gemm, cudaFuncAttributeMaxDynamicSharedMemorySize, SMEM_MAIN);

    {
        int total = OUT_DIM * K_TOTAL;
        prep_weff<<<(total + 255) / 256, 256>>>(bw, sw, ss, wh, wl);
    }
    {
        size_t n = (size_t)NODE_DIM * CTX_DIM;
        cvt_split<<<(int)((n + 255) / 256), 256>>>(ctxw, cwh, cwl, n);
    }
    {
        size_t n = (size_t)nEdges * CTX_DIM;
        cvt_split<<<(int)((n + 255) / 256), 256>>>(cemb, ceh, cel, n);
    }

    // ctx projection  xc = cemb @ ctxw^T + b  (M=nEdges, N=128, K=256)
    {
        dim3 g(1, (nEdges + 127) / 128);
        ctx_gemm<<<g, 256, SMEM_CTX>>>(ceh, cel, cwh, cwl, ctxb, xc,
                                       nEdges, NODE_DIM, CTX_DIM);
    }

    // activations (fp16)
    {
        int total = nEdges * IN_DIM;
        build_act<<<(total + 255) / 256, 256>>>(node, xc, pairs, grid, acth, actl, nEdges);
    }

    // main GEMM  out = act @ weff^T  (M=nEdges, N=256, K=3072)
    {
        dim3 g(OUT_DIM / 128, (nEdges + 127) / 128);
        main_gemm<<<g, 256, SMEM_MAIN>>>(acth, actl, wh, wl, out, nEdges);
    }
}

// round 9
// speedup vs baseline: 1.9627x; 1.1987x over previous
#include <cuda_runtime.h>
#include <cuda_bf16.h>
#include <cuda_fp16.h>
#include <cstdint>

// ---------------- problem constants ----------------
#define NODE_DIM 128
#define CTX_DIM  256
#define OUT_DIM  256
#define IN_DIM   384
#define N_COEF   7
#define K_TOTAL  3072        // coefficient-major: k<384 silu, k>=384: c*384+i
#define MAX_EDGES 100000

typedef __nv_bfloat16 bf16;

// ---------------- device scratch (static) ----------------
__device__ float g_xc[(size_t)MAX_EDGES * NODE_DIM];
__device__ half  g_act_h[(size_t)MAX_EDGES * K_TOTAL];    // 614 MB
__device__ half  g_act_l[(size_t)MAX_EDGES * IN_DIM];     // 77 MB (silu lo only)
__device__ half  g_w_h[(size_t)OUT_DIM * K_TOTAL];
__device__ half  g_w_l[(size_t)OUT_DIM * K_TOTAL];
__device__ bf16  g_cemb_hi[(size_t)MAX_EDGES * CTX_DIM];
__device__ bf16  g_cemb_lo[(size_t)MAX_EDGES * CTX_DIM];
__device__ bf16  g_cw_hi[(size_t)NODE_DIM * CTX_DIM];
__device__ bf16  g_cw_lo[(size_t)NODE_DIM * CTX_DIM];

// ---------------- helpers ----------------
__device__ __forceinline__ uint32_t smem_u32(const void* p) {
    uint32_t a;
    asm("{ .reg .u64 t; cvta.to.shared.u64 t, %1; cvt.u32.u64 %0, t; }" : "=r"(a) : "l"(p));
    return a;
}
#define SWZ(x) ((x) ^ (((x) >> 3) & 0x70))

__device__ __forceinline__ void cp16(uint32_t saddr, const void* g, uint32_t sz) {
    asm volatile("cp.async.cg.shared.global [%0], [%1], 16, %2;\n"
                 :: "r"(saddr), "l"(g), "r"(sz));
}
template <int N>
__device__ __forceinline__ void cp_wait() {
    asm volatile("cp.async.wait_group %0;\n" :: "n"(N) : "memory");
}
__device__ __forceinline__ void cp_commit() {
    asm volatile("cp.async.commit_group;\n" ::: "memory");
}

__device__ __forceinline__ void ldm4(uint32_t* r, uint32_t addr) {
    asm volatile("ldmatrix.sync.aligned.m8n8.x4.shared.b16 {%0,%1,%2,%3}, [%4];"
                 : "=r"(r[0]), "=r"(r[1]), "=r"(r[2]), "=r"(r[3]) : "r"(addr));
}

__device__ __forceinline__ void mma_bf16(float* d, const uint32_t* a, const uint32_t* b) {
    asm volatile(
        "mma.sync.aligned.m16n8k16.row.col.f32.bf16.bf16.f32 "
        "{%0,%1,%2,%3}, {%4,%5,%6,%7}, {%8,%9}, {%0,%1,%2,%3};"
        : "+f"(d[0]), "+f"(d[1]), "+f"(d[2]), "+f"(d[3])
        : "r"(a[0]), "r"(a[1]), "r"(a[2]), "r"(a[3]), "r"(b[0]), "r"(b[1]));
}
__device__ __forceinline__ void mma_f16(float* d, const uint32_t* a, const uint32_t* b) {
    asm volatile(
        "mma.sync.aligned.m16n8k16.row.col.f32.f16.f16.f32 "
        "{%0,%1,%2,%3}, {%4,%5,%6,%7}, {%8,%9}, {%0,%1,%2,%3};"
        : "+f"(d[0]), "+f"(d[1]), "+f"(d[2]), "+f"(d[3])
        : "r"(a[0]), "r"(a[1]), "r"(a[2]), "r"(a[3]), "r"(b[0]), "r"(b[1]));
}

// ---------------- weight prep: fp16 hi/lo, coefficient-major ---------------
__global__ void prep_weff(const float* __restrict__ bw, const float* __restrict__ sw,
                          const float* __restrict__ ss, half* __restrict__ Wh,
                          half* __restrict__ Wl)
{
    int t = blockIdx.x * blockDim.x + threadIdx.x;
    if (t >= OUT_DIM * K_TOTAL) return;
    int o = t / K_TOTAL;
    int k = t - o * K_TOTAL;
    float v;
    if (k < IN_DIM) v = bw[o * IN_DIM + k];
    else {
        int r = k - IN_DIM;
        int c = r / IN_DIM;
        int i = r - c * IN_DIM;
        v = sw[((size_t)o * IN_DIM + i) * N_COEF + c] * ss[o * IN_DIM + i];
    }
    half h = __float2half_rn(v);
    Wh[t] = h;
    Wl[t] = __float2half_rn(v - __half2float(h));
}

__global__ void cvt_split(const float* __restrict__ src, bf16* __restrict__ hi,
                          bf16* __restrict__ lo, size_t n)
{
    size_t t = (size_t)blockIdx.x * blockDim.x + threadIdx.x;
    if (t >= n) return;
    float v = src[t];
    bf16 h = __float2bfloat16(v);
    hi[t] = h;
    lo[t] = __float2bfloat16(v - __bfloat162float(h));
}

// ============ ctx GEMM: bf16 split 3-pass (proven, 256thr) ==================
#define TILE_BYTES 16384
#define OFF_AH 0
#define OFF_AL (TILE_BYTES)
#define OFF_BH (2 * TILE_BYTES)
#define OFF_BL (3 * TILE_BYTES)
#define STAGE_BYTES (4 * TILE_BYTES)
#define NSTAGE 3
#define SMEM_CTX (NSTAGE * STAGE_BYTES)

__global__ void __launch_bounds__(256, 1)
ctx_gemm(const bf16* __restrict__ Ah, const bf16* __restrict__ Al,
         const bf16* __restrict__ Bh, const bf16* __restrict__ Bl,
         const float* __restrict__ bias, float* __restrict__ C,
         int M, int N, int K)
{
    extern __shared__ char smem[];
    const uint32_t sbase = smem_u32(smem);
    const int tid = threadIdx.x;
    const int wid = tid >> 5;
    const int lid = tid & 31;
    const int m0 = blockIdx.y * 128;
    const int n0 = blockIdx.x * 128;
    const int warp_m = (wid >> 2) * 64;
    const int warp_n = (wid & 3) * 32;

    float acc[4][4][4];
#pragma unroll
    for (int i = 0; i < 4; ++i)
#pragma unroll
        for (int j = 0; j < 4; ++j)
#pragma unroll
            for (int q = 0; q < 4; ++q) acc[i][j][q] = 0.f;

    auto load_stage = [&](int t, int buf) {
        const uint32_t bb = sbase + buf * STAGE_BYTES;
        const int k0 = t * 64;
        for (int i = tid; i < 1024; i += 256) {
            int row = i >> 3, c = i & 7;
            int m = m0 + row;
            uint32_t v = (m < M) ? 16u : 0u;
            size_t go = (size_t)(m < M ? m : 0) * K + k0 + c * 8;
            uint32_t so = SWZ(row * 128 + c * 16);
            cp16(bb + OFF_AH + so, Ah + go, v);
            cp16(bb + OFF_AL + so, Al + go, v);
        }
        for (int i = tid; i < 1024; i += 256) {
            int row = i >> 3, c = i & 7;
            size_t go = (size_t)(n0 + row) * K + k0 + c * 8;
            uint32_t so = SWZ(row * 128 + c * 16);
            cp16(bb + OFF_BH + so, Bh + go, 16u);
            cp16(bb + OFF_BL + so, Bl + go, 16u);
        }
        cp_commit();
    };

    const int nk = K / 64;
    load_stage(0, 0);
    if (nk > 1) load_stage(1, 1);

    for (int t = 0; t < nk; ++t) {
        if (t < nk - 1) cp_wait<1>(); else cp_wait<0>();
        __syncthreads();
        if (t + 2 < nk) load_stage(t + 2, (t + 2) % NSTAGE);

        const uint32_t bb = sbase + (t % NSTAGE) * STAGE_BYTES;
#pragma unroll
        for (int ks = 0; ks < 4; ++ks) {
            uint32_t ah[4][4], al[4][4], bh[4][2], bl[4][2];
            {
                uint32_t row_in = ((lid >> 3) & 1) * 8 + (lid & 7);
                uint32_t kb = ks * 32 + (lid >> 4) * 16;
#pragma unroll
                for (int mf = 0; mf < 4; ++mf) {
                    uint32_t off = SWZ((warp_m + mf * 16 + row_in) * 128 + kb);
                    ldm4(ah[mf], bb + OFF_AH + off);
                    ldm4(al[mf], bb + OFF_AL + off);
                }
            }
            {
                uint32_t row_in = ((lid >> 4) & 1) * 8 + (lid & 7);
                uint32_t kb = ks * 32 + ((lid >> 3) & 1) * 16;
#pragma unroll
                for (int p = 0; p < 2; ++p) {
                    uint32_t off = SWZ((warp_n + p * 16 + row_in) * 128 + kb);
                    uint32_t r[4];
                    ldm4(r, bb + OFF_BH + off);
                    bh[2 * p][0] = r[0]; bh[2 * p][1] = r[1];
                    bh[2 * p + 1][0] = r[2]; bh[2 * p + 1][1] = r[3];
                    ldm4(r, bb + OFF_BL + off);
                    bl[2 * p][0] = r[0]; bl[2 * p][1] = r[1];
                    bl[2 * p + 1][0] = r[2]; bl[2 * p + 1][1] = r[3];
                }
            }
#pragma unroll
            for (int mf = 0; mf < 4; ++mf)
#pragma unroll
                for (int nf = 0; nf < 4; ++nf)
                    mma_bf16(acc[mf][nf], ah[mf], bh[nf]);
#pragma unroll
            for (int mf = 0; mf < 4; ++mf)
#pragma unroll
                for (int nf = 0; nf < 4; ++nf)
                    mma_bf16(acc[mf][nf], ah[mf], bl[nf]);
#pragma unroll
            for (int mf = 0; mf < 4; ++mf)
#pragma unroll
                for (int nf = 0; nf < 4; ++nf)
                    mma_bf16(acc[mf][nf], al[mf], bh[nf]);
        }
        __syncthreads();
    }

#pragma unroll
    for (int mf = 0; mf < 4; ++mf) {
        int r0 = m0 + warp_m + mf * 16 + (lid >> 2);
#pragma unroll
        for (int nf = 0; nf < 4; ++nf) {
            int col = n0 + warp_n + nf * 8 + (lid & 3) * 2;
            float b0 = bias ? bias[col] : 0.f;
            float b1 = bias ? bias[col + 1] : 0.f;
            if (r0 < M) {
                float2 v = make_float2(acc[mf][nf][0] + b0, acc[mf][nf][1] + b1);
                *reinterpret_cast<float2*>(&C[(size_t)r0 * N + col]) = v;
            }
            if (r0 + 8 < M) {
                float2 v = make_float2(acc[mf][nf][2] + b0, acc[mf][nf][3] + b1);
                *reinterpret_cast<float2*>(&C[(size_t)(r0 + 8) * N + col]) = v;
            }
        }
    }
}

// ============ main GEMM: fp16 hybrid, spline single-pass =====================
// chunks 0..5 (silu):   3 passes  Ah*Bh + Ah*Bl + Al*Bh   (fp16-split both)
// chunks 6..47 (spline): 1 pass   Ah*Bh                   (plain fp16)
#define MOFF_AH 0
#define MOFF_AL 16384
#define MOFF_BH 32768
#define MOFF_BL 49152
#define MSTAGE  65536
#define SMEM_MAIN (3 * 65536)     // 192 KB

__global__ void __launch_bounds__(256, 1)
main_gemm(const half* __restrict__ Ah, const half* __restrict__ Alo,
          const half* __restrict__ Bh, const half* __restrict__ Bl,
          float* __restrict__ C, int M)
{
    extern __shared__ char smem[];
    const uint32_t sbase = smem_u32(smem);
    const int tid = threadIdx.x;
    const int wid = tid >> 5;
    const int lid = tid & 31;
    const int m0 = blockIdx.y * 128;
    const int n0 = blockIdx.x * 128;
    const int warp_m = (wid >> 2) * 64;
    const int warp_n = (wid & 3) * 32;
    const int nk = K_TOTAL / 64;   // 48; silu = chunks 0..5

    float acc[4][4][4];
#pragma unroll
    for (int i = 0; i < 4; ++i)
#pragma unroll
        for (int j = 0; j < 4; ++j)
#pragma unroll
            for (int q = 0; q < 4; ++q) acc[i][j][q] = 0.f;

    auto load_stage = [&](int t, int buf) {
        const uint32_t bb = sbase + buf * MSTAGE;
        const int k0 = t * 64;
        const bool silu = (t < 6);
        for (int i = tid; i < 1024; i += 256) {
            int row = i >> 3, c = i & 7;
            int m = m0 + row;
            uint32_t v = (m < M) ? 16u : 0u;
            uint32_t so = SWZ(row * 128 + c * 16);
            cp16(bb + MOFF_AH + so,
                 Ah + (size_t)(m < M ? m : 0) * K_TOTAL + k0 + c * 8, v);
            if (silu)
                cp16(bb + MOFF_AL + so,
                     Alo + (size_t)(m < M ? m : 0) * IN_DIM + k0 + c * 8, v);
        }
        for (int i = tid; i < 1024; i += 256) {
            int row = i >> 3, c = i & 7;
            size_t go = (size_t)(n0 + row) * K_TOTAL + k0 + c * 8;
            uint32_t so = SWZ(row * 128 + c * 16);
            cp16(bb + MOFF_BH + so, Bh + go, 16u);
            if (silu) cp16(bb + MOFF_BL + so, Bl + go, 16u);
        }
        cp_commit();
    };

    load_stage(0, 0);
    load_stage(1, 1);

    for (int t = 0; t < nk; ++t) {
        if (t < nk - 1) cp_wait<1>(); else cp_wait<0>();
        __syncthreads();   // stage t ready; all warps done reading stage t-1
        if (t + 2 < nk) load_stage(t + 2, (t + 2) % 3);

        const uint32_t bb = sbase + (t % 3) * MSTAGE;
        const bool silu = (t < 6);
#pragma unroll
        for (int ks = 0; ks < 4; ++ks) {
            uint32_t ah[4][4], al[4][4], bh[4][2], bl[4][2];
            {
                uint32_t row_in = ((lid >> 3) & 1) * 8 + (lid & 7);
                uint32_t kb = ks * 32 + (lid >> 4) * 16;
#pragma unroll
                for (int mf = 0; mf < 4; ++mf) {
                    uint32_t off = SWZ((warp_m + mf * 16 + row_in) * 128 + kb);
                    ldm4(ah[mf], bb + MOFF_AH + off);
                    if (silu) ldm4(al[mf], bb + MOFF_AL + off);
                }
            }
            {
                uint32_t row_in = ((lid >> 4) & 1) * 8 + (lid & 7);
                uint32_t kb = ks * 32 + ((lid >> 3) & 1) * 16;
#pragma unroll
                for (int p = 0; p < 2; ++p) {
                    uint32_t off = SWZ((warp_n + p * 16 + row_in) * 128 + kb);
                    uint32_t r[4];
                    ldm4(r, bb + MOFF_BH + off);
                    bh[2 * p][0] = r[0]; bh[2 * p][1] = r[1];
                    bh[2 * p + 1][0] = r[2]; bh[2 * p + 1][1] = r[3];
                    if (silu) {
                        ldm4(r, bb + MOFF_BL + off);
                        bl[2 * p][0] = r[0]; bl[2 * p][1] = r[1];
                        bl[2 * p + 1][0] = r[2]; bl[2 * p + 1][1] = r[3];
                    }
                }
            }
#pragma unroll
            for (int mf = 0; mf < 4; ++mf)
#pragma unroll
                for (int nf = 0; nf < 4; ++nf)
                    mma_f16(acc[mf][nf], ah[mf], bh[nf]);
            if (silu) {
#pragma unroll
                for (int mf = 0; mf < 4; ++mf)
#pragma unroll
                    for (int nf = 0; nf < 4; ++nf)
                        mma_f16(acc[mf][nf], ah[mf], bl[nf]);
#pragma unroll
                for (int mf = 0; mf < 4; ++mf)
#pragma unroll
                    for (int nf = 0; nf < 4; ++nf)
                        mma_f16(acc[mf][nf], al[mf], bh[nf]);
            }
        }
    }

#pragma unroll
    for (int mf = 0; mf < 4; ++mf) {
        int r0 = m0 + warp_m + mf * 16 + (lid >> 2);
#pragma unroll
        for (int nf = 0; nf < 4; ++nf) {
            int col = n0 + warp_n + nf * 8 + (lid & 3) * 2;
            if (r0 < M) {
                float2 v = make_float2(acc[mf][nf][0], acc[mf][nf][1]);
                *reinterpret_cast<float2*>(&C[(size_t)r0 * OUT_DIM + col]) = v;
            }
            if (r0 + 8 < M) {
                float2 v = make_float2(acc[mf][nf][2], acc[mf][nf][3]);
                *reinterpret_cast<float2*>(&C[(size_t)(r0 + 8) * OUT_DIM + col]) = v;
            }
        }
    }
}

// ---------------- activation builder (fp16, silu lo separate) ---------------
__global__ void build_act(const float* __restrict__ node, const float* __restrict__ xc,
                          const int* __restrict__ pairs, const float* __restrict__ grid,
                          half* __restrict__ acth, half* __restrict__ actl, int nEdges)
{
    __shared__ float g[11];
    __shared__ float inv[3][11];
    if (threadIdx.x < 11) g[threadIdx.x] = grid[threadIdx.x];  // grid rows identical
    __syncthreads();
    if (threadIdx.x < 11) {
        int j = threadIdx.x;
#pragma unroll
        for (int k = 1; k <= 3; ++k)
            if (j <= 10 - k) inv[k - 1][j] = 1.f / (g[j + k] - g[j]);
    }
    __syncthreads();

    int t = blockIdx.x * blockDim.x + threadIdx.x;
    if (t >= nEdges * IN_DIM) return;
    int n = t / IN_DIM;
    int i = t - n * IN_DIM;

    float x;
    if (i < NODE_DIM) {
        int p = pairs[2 * n];
        x = node[(size_t)p * NODE_DIM + i];
    } else if (i < 2 * NODE_DIM) {
        int p = pairs[2 * n + 1];
        x = node[(size_t)p * NODE_DIM + (i - NODE_DIM)];
    } else {
        x = xc[(size_t)n * NODE_DIM + (i - 2 * NODE_DIM)];
    }

    float s = x / (1.f + expf(-x));

    float b[10];
#pragma unroll
    for (int j = 0; j < 10; ++j) b[j] = (x >= g[j] && x < g[j + 1]) ? 1.f : 0.f;
#pragma unroll
    for (int k = 1; k <= 3; ++k) {
#pragma unroll
        for (int j = 0; j < 10; ++j) {
            if (j < 10 - k) {
                b[j] = (x - g[j]) * inv[k - 1][j] * b[j]
                     + (g[j + k + 1] - x) * inv[k - 1][j + 1] * b[j + 1];
            }
        }
    }

    size_t base = (size_t)n * K_TOTAL;
    {
        half h = __float2half_rn(s);
        acth[base + i] = h;
        actl[(size_t)n * IN_DIM + i] = __float2half_rn(s - __half2float(h));
    }
#pragma unroll
    for (int c = 0; c < N_COEF; ++c)
        acth[base + IN_DIM + (size_t)c * IN_DIM + i] = __float2half_rn(b[c]);
}

// ---------------------------------------------------------------------------
extern "C" void kernel_launch(void* const* d_in, const int* in_sizes, int n_in,
                              void* d_out, int out_size)
{
    const float* node  = (const float*)d_in[0];
    const float* cemb  = (const float*)d_in[1];
    const int*   pairs = (const int*)  d_in[2];
    const float* ctxw  = (const float*)d_in[3];
    const float* ctxb  = (const float*)d_in[4];
    const float* bw    = (const float*)d_in[5];
    const float* sw    = (const float*)d_in[6];
    const float* ss    = (const float*)d_in[7];
    const float* grid  = (const float*)d_in[8];
    float* out = (float*)d_out;

    int nEdges = in_sizes[2] / 2;

    float *xc;
    half *acth, *actl, *wh, *wl;
    bf16 *ceh, *cel, *cwh, *cwl;
    cudaGetSymbolAddress((void**)&xc, g_xc);
    cudaGetSymbolAddress((void**)&acth, g_act_h);
    cudaGetSymbolAddress((void**)&actl, g_act_l);
    cudaGetSymbolAddress((void**)&wh, g_w_h);
    cudaGetSymbolAddress((void**)&wl, g_w_l);
    cudaGetSymbolAddress((void**)&ceh, g_cemb_hi);
    cudaGetSymbolAddress((void**)&cel, g_cemb_lo);
    cudaGetSymbolAddress((void**)&cwh, g_cw_hi);
    cudaGetSymbolAddress((void**)&cwl, g_cw_lo);

    cudaFuncSetAttribute(ctx_gemm, cudaFuncAttributeMaxDynamicSharedMemorySize, SMEM_CTX);
    cudaFuncSetAttribute(main_gemm, cudaFuncAttributeMaxDynamicSharedMemorySize, SMEM_MAIN);

    {
        int total = OUT_DIM * K_TOTAL;
        prep_weff<<<(total + 255) / 256, 256>>>(bw, sw, ss, wh, wl);
    }
    {
        size_t n = (size_t)NODE_DIM * CTX_DIM;
        cvt_split<<<(int)((n + 255) / 256), 256>>>(ctxw, cwh, cwl, n);
    }
    {
        size_t n = (size_t)nEdges * CTX_DIM;
        cvt_split<<<(int)((n + 255) / 256), 256>>>(cemb, ceh, cel, n);
    }

    // ctx projection  xc = cemb @ ctxw^T + b  (M=nEdges, N=128, K=256)
    {
        dim3 g(1, (nEdges + 127) / 128);
        ctx_gemm<<<g, 256, SMEM_CTX>>>(ceh, cel, cwh, cwl, ctxb, xc,
                                       nEdges, NODE_DIM, CTX_DIM);
    }

    // activations (fp16)
    {
        int total = nEdges * IN_DIM;
        build_act<<<(total + 255) / 256, 256>>>(node, xc, pairs, grid, acth, actl, nEdges);
    }

    // main GEMM  out = act @ weff^T  (M=nEdges, N=256, K=3072)
    {
        dim3 g(OUT_DIM / 128, (nEdges + 127) / 128);
        main_gemm<<<g, 256, SMEM_MAIN>>>(acth, actl, wh, wl, out, nEdges);
    }
}

// round 10
// speedup vs baseline: 2.4883x; 1.2678x over previous
#include <cuda_runtime.h>
#include <cuda_bf16.h>
#include <cuda_fp16.h>
#include <cstdint>

// ---------------- problem constants ----------------
#define NODE_DIM 128
#define CTX_DIM  256
#define OUT_DIM  256
#define IN_DIM   384
#define N_COEF   7
#define K_TOTAL  3072        // coefficient-major: k<384 silu, k>=384: c*384+i
#define MAX_EDGES 100000

typedef __nv_bfloat16 bf16;

// ---------------- device scratch (static) ----------------
__device__ float g_xc[(size_t)MAX_EDGES * NODE_DIM];
__device__ half  g_act_h[(size_t)MAX_EDGES * K_TOTAL];    // 614 MB
__device__ half  g_w_h[(size_t)OUT_DIM * K_TOTAL];
__device__ bf16  g_cemb_hi[(size_t)MAX_EDGES * CTX_DIM];
__device__ bf16  g_cemb_lo[(size_t)MAX_EDGES * CTX_DIM];
__device__ bf16  g_cw_hi[(size_t)NODE_DIM * CTX_DIM];
__device__ bf16  g_cw_lo[(size_t)NODE_DIM * CTX_DIM];

// ---------------- helpers ----------------
__device__ __forceinline__ uint32_t smem_u32(const void* p) {
    uint32_t a;
    asm("{ .reg .u64 t; cvta.to.shared.u64 t, %1; cvt.u32.u64 %0, t; }" : "=r"(a) : "l"(p));
    return a;
}
#define SWZ(x) ((x) ^ (((x) >> 3) & 0x70))

__device__ __forceinline__ void cp16(uint32_t saddr, const void* g, uint32_t sz) {
    asm volatile("cp.async.cg.shared.global [%0], [%1], 16, %2;\n"
                 :: "r"(saddr), "l"(g), "r"(sz));
}
template <int N>
__device__ __forceinline__ void cp_wait() {
    asm volatile("cp.async.wait_group %0;\n" :: "n"(N) : "memory");
}
__device__ __forceinline__ void cp_commit() {
    asm volatile("cp.async.commit_group;\n" ::: "memory");
}

__device__ __forceinline__ void ldm4(uint32_t* r, uint32_t addr) {
    asm volatile("ldmatrix.sync.aligned.m8n8.x4.shared.b16 {%0,%1,%2,%3}, [%4];"
                 : "=r"(r[0]), "=r"(r[1]), "=r"(r[2]), "=r"(r[3]) : "r"(addr));
}

__device__ __forceinline__ void mma_bf16(float* d, const uint32_t* a, const uint32_t* b) {
    asm volatile(
        "mma.sync.aligned.m16n8k16.row.col.f32.bf16.bf16.f32 "
        "{%0,%1,%2,%3}, {%4,%5,%6,%7}, {%8,%9}, {%0,%1,%2,%3};"
        : "+f"(d[0]), "+f"(d[1]), "+f"(d[2]), "+f"(d[3])
        : "r"(a[0]), "r"(a[1]), "r"(a[2]), "r"(a[3]), "r"(b[0]), "r"(b[1]));
}
__device__ __forceinline__ void mma_f16(float* d, const uint32_t* a, const uint32_t* b) {
    asm volatile(
        "mma.sync.aligned.m16n8k16.row.col.f32.f16.f16.f32 "
        "{%0,%1,%2,%3}, {%4,%5,%6,%7}, {%8,%9}, {%0,%1,%2,%3};"
        : "+f"(d[0]), "+f"(d[1]), "+f"(d[2]), "+f"(d[3])
        : "r"(a[0]), "r"(a[1]), "r"(a[2]), "r"(a[3]), "r"(b[0]), "r"(b[1]));
}

// ---------------- weight prep: plain fp16, coefficient-major ---------------
__global__ void prep_weff(const float* __restrict__ bw, const float* __restrict__ sw,
                          const float* __restrict__ ss, half* __restrict__ Wh)
{
    int t = blockIdx.x * blockDim.x + threadIdx.x;
    if (t >= OUT_DIM * K_TOTAL) return;
    int o = t / K_TOTAL;
    int k = t - o * K_TOTAL;
    float v;
    if (k < IN_DIM) v = bw[o * IN_DIM + k];
    else {
        int r = k - IN_DIM;
        int c = r / IN_DIM;
        int i = r - c * IN_DIM;
        v = sw[((size_t)o * IN_DIM + i) * N_COEF + c] * ss[o * IN_DIM + i];
    }
    Wh[t] = __float2half_rn(v);
}

__global__ void cvt_split(const float* __restrict__ src, bf16* __restrict__ hi,
                          bf16* __restrict__ lo, size_t n)
{
    size_t t = (size_t)blockIdx.x * blockDim.x + threadIdx.x;
    if (t >= n) return;
    float v = src[t];
    bf16 h = __float2bfloat16(v);
    hi[t] = h;
    lo[t] = __float2bfloat16(v - __bfloat162float(h));
}

// ============ ctx GEMM: bf16 split 3-pass (proven, 256thr) ==================
#define TILE_BYTES 16384
#define OFF_AH 0
#define OFF_AL (TILE_BYTES)
#define OFF_BH (2 * TILE_BYTES)
#define OFF_BL (3 * TILE_BYTES)
#define STAGE_BYTES (4 * TILE_BYTES)
#define NSTAGE 3
#define SMEM_CTX (NSTAGE * STAGE_BYTES)

__global__ void __launch_bounds__(256, 1)
ctx_gemm(const bf16* __restrict__ Ah, const bf16* __restrict__ Al,
         const bf16* __restrict__ Bh, const bf16* __restrict__ Bl,
         const float* __restrict__ bias, float* __restrict__ C,
         int M, int N, int K)
{
    extern __shared__ char smem[];
    const uint32_t sbase = smem_u32(smem);
    const int tid = threadIdx.x;
    const int wid = tid >> 5;
    const int lid = tid & 31;
    const int m0 = blockIdx.y * 128;
    const int n0 = blockIdx.x * 128;
    const int warp_m = (wid >> 2) * 64;
    const int warp_n = (wid & 3) * 32;

    float acc[4][4][4];
#pragma unroll
    for (int i = 0; i < 4; ++i)
#pragma unroll
        for (int j = 0; j < 4; ++j)
#pragma unroll
            for (int q = 0; q < 4; ++q) acc[i][j][q] = 0.f;

    auto load_stage = [&](int t, int buf) {
        const uint32_t bb = sbase + buf * STAGE_BYTES;
        const int k0 = t * 64;
        for (int i = tid; i < 1024; i += 256) {
            int row = i >> 3, c = i & 7;
            int m = m0 + row;
            uint32_t v = (m < M) ? 16u : 0u;
            size_t go = (size_t)(m < M ? m : 0) * K + k0 + c * 8;
            uint32_t so = SWZ(row * 128 + c * 16);
            cp16(bb + OFF_AH + so, Ah + go, v);
            cp16(bb + OFF_AL + so, Al + go, v);
        }
        for (int i = tid; i < 1024; i += 256) {
            int row = i >> 3, c = i & 7;
            size_t go = (size_t)(n0 + row) * K + k0 + c * 8;
            uint32_t so = SWZ(row * 128 + c * 16);
            cp16(bb + OFF_BH + so, Bh + go, 16u);
            cp16(bb + OFF_BL + so, Bl + go, 16u);
        }
        cp_commit();
    };

    const int nk = K / 64;
    load_stage(0, 0);
    if (nk > 1) load_stage(1, 1);

    for (int t = 0; t < nk; ++t) {
        if (t < nk - 1) cp_wait<1>(); else cp_wait<0>();
        __syncthreads();
        if (t + 2 < nk) load_stage(t + 2, (t + 2) % NSTAGE);

        const uint32_t bb = sbase + (t % NSTAGE) * STAGE_BYTES;
#pragma unroll
        for (int ks = 0; ks < 4; ++ks) {
            uint32_t ah[4][4], al[4][4], bh[4][2], bl[4][2];
            {
                uint32_t row_in = ((lid >> 3) & 1) * 8 + (lid & 7);
                uint32_t kb = ks * 32 + (lid >> 4) * 16;
#pragma unroll
                for (int mf = 0; mf < 4; ++mf) {
                    uint32_t off = SWZ((warp_m + mf * 16 + row_in) * 128 + kb);
                    ldm4(ah[mf], bb + OFF_AH + off);
                    ldm4(al[mf], bb + OFF_AL + off);
                }
            }
            {
                uint32_t row_in = ((lid >> 4) & 1) * 8 + (lid & 7);
                uint32_t kb = ks * 32 + ((lid >> 3) & 1) * 16;
#pragma unroll
                for (int p = 0; p < 2; ++p) {
                    uint32_t off = SWZ((warp_n + p * 16 + row_in) * 128 + kb);
                    uint32_t r[4];
                    ldm4(r, bb + OFF_BH + off);
                    bh[2 * p][0] = r[0]; bh[2 * p][1] = r[1];
                    bh[2 * p + 1][0] = r[2]; bh[2 * p + 1][1] = r[3];
                    ldm4(r, bb + OFF_BL + off);
                    bl[2 * p][0] = r[0]; bl[2 * p][1] = r[1];
                    bl[2 * p + 1][0] = r[2]; bl[2 * p + 1][1] = r[3];
                }
            }
#pragma unroll
            for (int mf = 0; mf < 4; ++mf)
#pragma unroll
                for (int nf = 0; nf < 4; ++nf)
                    mma_bf16(acc[mf][nf], ah[mf], bh[nf]);
#pragma unroll
            for (int mf = 0; mf < 4; ++mf)
#pragma unroll
                for (int nf = 0; nf < 4; ++nf)
                    mma_bf16(acc[mf][nf], ah[mf], bl[nf]);
#pragma unroll
            for (int mf = 0; mf < 4; ++mf)
#pragma unroll
                for (int nf = 0; nf < 4; ++nf)
                    mma_bf16(acc[mf][nf], al[mf], bh[nf]);
        }
        __syncthreads();
    }

#pragma unroll
    for (int mf = 0; mf < 4; ++mf) {
        int r0 = m0 + warp_m + mf * 16 + (lid >> 2);
#pragma unroll
        for (int nf = 0; nf < 4; ++nf) {
            int col = n0 + warp_n + nf * 8 + (lid & 3) * 2;
            float b0 = bias ? bias[col] : 0.f;
            float b1 = bias ? bias[col + 1] : 0.f;
            if (r0 < M) {
                float2 v = make_float2(acc[mf][nf][0] + b0, acc[mf][nf][1] + b1);
                *reinterpret_cast<float2*>(&C[(size_t)r0 * N + col]) = v;
            }
            if (r0 + 8 < M) {
                float2 v = make_float2(acc[mf][nf][2] + b0, acc[mf][nf][3] + b1);
                *reinterpret_cast<float2*>(&C[(size_t)(r0 + 8) * N + col]) = v;
            }
        }
    }
}

// ============ main GEMM: plain fp16 single pass ==============================
// out = act_fp16 @ W_fp16^T, fp32 accumulate. Stage = AH 16K + BH 16K = 32 KB.
// 3 stages = 96 KB -> 2 CTAs/SM.
#define MOFF_AH 0
#define MOFF_BH 16384
#define MSTAGE  32768
#define SMEM_MAIN (3 * 32768)     // 96 KB

__global__ void __launch_bounds__(256, 2)
main_gemm(const half* __restrict__ Ah, const half* __restrict__ Bh,
          float* __restrict__ C, int M)
{
    extern __shared__ char smem[];
    const uint32_t sbase = smem_u32(smem);
    const int tid = threadIdx.x;
    const int wid = tid >> 5;
    const int lid = tid & 31;
    const int m0 = blockIdx.y * 128;
    const int n0 = blockIdx.x * 128;
    const int warp_m = (wid >> 2) * 64;
    const int warp_n = (wid & 3) * 32;
    const int nk = K_TOTAL / 64;   // 48

    float acc[4][4][4];
#pragma unroll
    for (int i = 0; i < 4; ++i)
#pragma unroll
        for (int j = 0; j < 4; ++j)
#pragma unroll
            for (int q = 0; q < 4; ++q) acc[i][j][q] = 0.f;

    auto load_stage = [&](int t, int buf) {
        const uint32_t bb = sbase + buf * MSTAGE;
        const int k0 = t * 64;
        for (int i = tid; i < 1024; i += 256) {
            int row = i >> 3, c = i & 7;
            int m = m0 + row;
            uint32_t v = (m < M) ? 16u : 0u;
            uint32_t so = SWZ(row * 128 + c * 16);
            cp16(bb + MOFF_AH + so,
                 Ah + (size_t)(m < M ? m : 0) * K_TOTAL + k0 + c * 8, v);
        }
        for (int i = tid; i < 1024; i += 256) {
            int row = i >> 3, c = i & 7;
            size_t go = (size_t)(n0 + row) * K_TOTAL + k0 + c * 8;
            uint32_t so = SWZ(row * 128 + c * 16);
            cp16(bb + MOFF_BH + so, Bh + go, 16u);
        }
        cp_commit();
    };

    load_stage(0, 0);
    load_stage(1, 1);

    for (int t = 0; t < nk; ++t) {
        if (t < nk - 1) cp_wait<1>(); else cp_wait<0>();
        __syncthreads();   // stage t ready; all warps done reading stage t-1
        if (t + 2 < nk) load_stage(t + 2, (t + 2) % 3);

        const uint32_t bb = sbase + (t % 3) * MSTAGE;
#pragma unroll
        for (int ks = 0; ks < 4; ++ks) {
            uint32_t ah[4][4], bh[4][2];
            {
                uint32_t row_in = ((lid >> 3) & 1) * 8 + (lid & 7);
                uint32_t kb = ks * 32 + (lid >> 4) * 16;
#pragma unroll
                for (int mf = 0; mf < 4; ++mf) {
                    uint32_t off = SWZ((warp_m + mf * 16 + row_in) * 128 + kb);
                    ldm4(ah[mf], bb + MOFF_AH + off);
                }
            }
            {
                uint32_t row_in = ((lid >> 4) & 1) * 8 + (lid & 7);
                uint32_t kb = ks * 32 + ((lid >> 3) & 1) * 16;
#pragma unroll
                for (int p = 0; p < 2; ++p) {
                    uint32_t off = SWZ((warp_n + p * 16 + row_in) * 128 + kb);
                    uint32_t r[4];
                    ldm4(r, bb + MOFF_BH + off);
                    bh[2 * p][0] = r[0]; bh[2 * p][1] = r[1];
                    bh[2 * p + 1][0] = r[2]; bh[2 * p + 1][1] = r[3];
                }
            }
#pragma unroll
            for (int mf = 0; mf < 4; ++mf)
#pragma unroll
                for (int nf = 0; nf < 4; ++nf)
                    mma_f16(acc[mf][nf], ah[mf], bh[nf]);
        }
    }

#pragma unroll
    for (int mf = 0; mf < 4; ++mf) {
        int r0 = m0 + warp_m + mf * 16 + (lid >> 2);
#pragma unroll
        for (int nf = 0; nf < 4; ++nf) {
            int col = n0 + warp_n + nf * 8 + (lid & 3) * 2;
            if (r0 < M) {
                float2 v = make_float2(acc[mf][nf][0], acc[mf][nf][1]);
                *reinterpret_cast<float2*>(&C[(size_t)r0 * OUT_DIM + col]) = v;
            }
            if (r0 + 8 < M) {
                float2 v = make_float2(acc[mf][nf][2], acc[mf][nf][3]);
                *reinterpret_cast<float2*>(&C[(size_t)(r0 + 8) * OUT_DIM + col]) = v;
            }
        }
    }
}

// ---------------- activation builder (plain fp16) ---------------------------
__global__ void build_act(const float* __restrict__ node, const float* __restrict__ xc,
                          const int* __restrict__ pairs, const float* __restrict__ grid,
                          half* __restrict__ acth, int nEdges)
{
    __shared__ float g[11];
    __shared__ float inv[3][11];
    if (threadIdx.x < 11) g[threadIdx.x] = grid[threadIdx.x];  // grid rows identical
    __syncthreads();
    if (threadIdx.x < 11) {
        int j = threadIdx.x;
#pragma unroll
        for (int k = 1; k <= 3; ++k)
            if (j <= 10 - k) inv[k - 1][j] = 1.f / (g[j + k] - g[j]);
    }
    __syncthreads();

    int t = blockIdx.x * blockDim.x + threadIdx.x;
    if (t >= nEdges * IN_DIM) return;
    int n = t / IN_DIM;
    int i = t - n * IN_DIM;

    float x;
    if (i < NODE_DIM) {
        int p = pairs[2 * n];
        x = node[(size_t)p * NODE_DIM + i];
    } else if (i < 2 * NODE_DIM) {
        int p = pairs[2 * n + 1];
        x = node[(size_t)p * NODE_DIM + (i - NODE_DIM)];
    } else {
        x = xc[(size_t)n * NODE_DIM + (i - 2 * NODE_DIM)];
    }

    float s = x / (1.f + expf(-x));

    float b[10];
#pragma unroll
    for (int j = 0; j < 10; ++j) b[j] = (x >= g[j] && x < g[j + 1]) ? 1.f : 0.f;
#pragma unroll
    for (int k = 1; k <= 3; ++k) {
#pragma unroll
        for (int j = 0; j < 10; ++j) {
            if (j < 10 - k) {
                b[j] = (x - g[j]) * inv[k - 1][j] * b[j]
                     + (g[j + k + 1] - x) * inv[k - 1][j + 1] * b[j + 1];
            }
        }
    }

    size_t base = (size_t)n * K_TOTAL;
    acth[base + i] = __float2half_rn(s);
#pragma unroll
    for (int c = 0; c < N_COEF; ++c)
        acth[base + IN_DIM + (size_t)c * IN_DIM + i] = __float2half_rn(b[c]);
}

// ---------------------------------------------------------------------------
extern "C" void kernel_launch(void* const* d_in, const int* in_sizes, int n_in,
                              void* d_out, int out_size)
{
    const float* node  = (const float*)d_in[0];
    const float* cemb  = (const float*)d_in[1];
    const int*   pairs = (const int*)  d_in[2];
    const float* ctxw  = (const float*)d_in[3];
    const float* ctxb  = (const float*)d_in[4];
    const float* bw    = (const float*)d_in[5];
    const float* sw    = (const float*)d_in[6];
    const float* ss    = (const float*)d_in[7];
    const float* grid  = (const float*)d_in[8];
    float* out = (float*)d_out;

    int nEdges = in_sizes[2] / 2;

    float *xc;
    half *acth, *wh;
    bf16 *ceh, *cel, *cwh, *cwl;
    cudaGetSymbolAddress((void**)&xc, g_xc);
    cudaGetSymbolAddress((void**)&acth, g_act_h);
    cudaGetSymbolAddress((void**)&wh, g_w_h);
    cudaGetSymbolAddress((void**)&ceh, g_cemb_hi);
    cudaGetSymbolAddress((void**)&cel, g_cemb_lo);
    cudaGetSymbolAddress((void**)&cwh, g_cw_hi);
    cudaGetSymbolAddress((void**)&cwl, g_cw_lo);

    cudaFuncSetAttribute(ctx_gemm, cudaFuncAttributeMaxDynamicSharedMemorySize, SMEM_CTX);
    cudaFuncSetAttribute(main_gemm, cudaFuncAttributeMaxDynamicSharedMemorySize, SMEM_MAIN);

    {
        int total = OUT_DIM * K_TOTAL;
        prep_weff<<<(total + 255) / 256, 256>>>(bw, sw, ss, wh);
    }
    {
        size_t n = (size_t)NODE_DIM * CTX_DIM;
        cvt_split<<<(int)((n + 255) / 256), 256>>>(ctxw, cwh, cwl, n);
    }
    {
        size_t n = (size_t)nEdges * CTX_DIM;
        cvt_split<<<(int)((n + 255) / 256), 256>>>(cemb, ceh, cel, n);
    }

    // ctx projection  xc = cemb @ ctxw^T + b  (M=nEdges, N=128, K=256)
    {
        dim3 g(1, (nEdges + 127) / 128);
        ctx_gemm<<<g, 256, SMEM_CTX>>>(ceh, cel, cwh, cwl, ctxb, xc,
                                       nEdges, NODE_DIM, CTX_DIM);
    }

    // activations (fp16)
    {
        int total = nEdges * IN_DIM;
        build_act<<<(total + 255) / 256, 256>>>(node, xc, pairs, grid, acth, nEdges);
    }

    // main GEMM  out = act @ weff^T  (M=nEdges, N=256, K=3072)
    {
        dim3 g(OUT_DIM / 128, (nEdges + 127) / 128);
        main_gemm<<<g, 256, SMEM_MAIN>>>(acth, wh, out, nEdges);
    }
}

// round 11
// speedup vs baseline: 3.6061x; 1.4493x over previous
#include <cuda_runtime.h>
#include <cuda_bf16.h>
#include <cuda_fp16.h>
#include <cstdint>

// ---------------- problem constants ----------------
#define NODE_DIM 128
#define CTX_DIM  256
#define OUT_DIM  256
#define IN_DIM   384
#define N_COEF   7
#define K_TOTAL  3072        // coefficient-major: k<384 silu, k>=384: c*384+i
#define MAX_EDGES 100000

typedef __nv_bfloat16 bf16;

// ---------------- device scratch (static) ----------------
__device__ float g_xc[(size_t)MAX_EDGES * NODE_DIM];
__device__ half  g_act_h[(size_t)MAX_EDGES * K_TOTAL];    // 614 MB
__device__ half  g_w_h[(size_t)OUT_DIM * K_TOTAL];
__device__ bf16  g_cemb_hi[(size_t)MAX_EDGES * CTX_DIM];
__device__ bf16  g_cemb_lo[(size_t)MAX_EDGES * CTX_DIM];
__device__ bf16  g_cw_hi[(size_t)NODE_DIM * CTX_DIM];
__device__ bf16  g_cw_lo[(size_t)NODE_DIM * CTX_DIM];

// ---------------- helpers ----------------
__device__ __forceinline__ uint32_t smem_u32(const void* p) {
    uint32_t a;
    asm("{ .reg .u64 t; cvta.to.shared.u64 t, %1; cvt.u32.u64 %0, t; }" : "=r"(a) : "l"(p));
    return a;
}
#define SWZ(x) ((x) ^ (((x) >> 3) & 0x70))

__device__ __forceinline__ void cp16(uint32_t saddr, const void* g, uint32_t sz) {
    asm volatile("cp.async.cg.shared.global [%0], [%1], 16, %2;\n"
                 :: "r"(saddr), "l"(g), "r"(sz));
}
template <int N>
__device__ __forceinline__ void cp_wait() {
    asm volatile("cp.async.wait_group %0;\n" :: "n"(N) : "memory");
}
__device__ __forceinline__ void cp_commit() {
    asm volatile("cp.async.commit_group;\n" ::: "memory");
}

__device__ __forceinline__ void ldm4(uint32_t* r, uint32_t addr) {
    asm volatile("ldmatrix.sync.aligned.m8n8.x4.shared.b16 {%0,%1,%2,%3}, [%4];"
                 : "=r"(r[0]), "=r"(r[1]), "=r"(r[2]), "=r"(r[3]) : "r"(addr));
}

__device__ __forceinline__ void mma_bf16(float* d, const uint32_t* a, const uint32_t* b) {
    asm volatile(
        "mma.sync.aligned.m16n8k16.row.col.f32.bf16.bf16.f32 "
        "{%0,%1,%2,%3}, {%4,%5,%6,%7}, {%8,%9}, {%0,%1,%2,%3};"
        : "+f"(d[0]), "+f"(d[1]), "+f"(d[2]), "+f"(d[3])
        : "r"(a[0]), "r"(a[1]), "r"(a[2]), "r"(a[3]), "r"(b[0]), "r"(b[1]));
}
__device__ __forceinline__ void mma_f16(float* d, const uint32_t* a, const uint32_t* b) {
    asm volatile(
        "mma.sync.aligned.m16n8k16.row.col.f32.f16.f16.f32 "
        "{%0,%1,%2,%3}, {%4,%5,%6,%7}, {%8,%9}, {%0,%1,%2,%3};"
        : "+f"(d[0]), "+f"(d[1]), "+f"(d[2]), "+f"(d[3])
        : "r"(a[0]), "r"(a[1]), "r"(a[2]), "r"(a[3]), "r"(b[0]), "r"(b[1]));
}

__device__ __forceinline__ uint32_t pack_half2(float lo, float hi) {
    __half2 h;
    h.x = __float2half_rn(lo);
    h.y = __float2half_rn(hi);
    return *reinterpret_cast<uint32_t*>(&h);
}
__device__ __forceinline__ uint32_t pack_bf2(float lo, float hi) {
    __nv_bfloat162 h;
    h.x = __float2bfloat16(lo);
    h.y = __float2bfloat16(hi);
    return *reinterpret_cast<uint32_t*>(&h);
}

// ---------------- weight prep: plain fp16, coefficient-major ---------------
__global__ void prep_weff(const float* __restrict__ bw, const float* __restrict__ sw,
                          const float* __restrict__ ss, half* __restrict__ Wh)
{
    int t = blockIdx.x * blockDim.x + threadIdx.x;
    if (t >= OUT_DIM * K_TOTAL) return;
    int o = t / K_TOTAL;
    int k = t - o * K_TOTAL;
    float v;
    if (k < IN_DIM) v = bw[o * IN_DIM + k];
    else {
        int r = k - IN_DIM;
        int c = r / IN_DIM;
        int i = r - c * IN_DIM;
        v = sw[((size_t)o * IN_DIM + i) * N_COEF + c] * ss[o * IN_DIM + i];
    }
    Wh[t] = __float2half_rn(v);
}

// ---------------- fp32 -> bf16 hi/lo split, 4 elems per thread --------------
__global__ void cvt_split4(const float* __restrict__ src, bf16* __restrict__ hi,
                           bf16* __restrict__ lo, size_t n4)
{
    size_t t = (size_t)blockIdx.x * blockDim.x + threadIdx.x;
    if (t >= n4) return;
    float4 v = *reinterpret_cast<const float4*>(src + t * 4);
    float f[4] = {v.x, v.y, v.z, v.w};
    float h[4], l[4];
#pragma unroll
    for (int q = 0; q < 4; ++q) {
        bf16 b = __float2bfloat16(f[q]);
        h[q] = __bfloat162float(b);
        l[q] = f[q] - h[q];
    }
    uint2 ho = make_uint2(pack_bf2(h[0], h[1]), pack_bf2(h[2], h[3]));
    uint2 loo = make_uint2(pack_bf2(l[0], l[1]), pack_bf2(l[2], l[3]));
    *reinterpret_cast<uint2*>(hi + t * 4) = ho;
    *reinterpret_cast<uint2*>(lo + t * 4) = loo;
}

// ============ ctx GEMM: bf16 split 3-pass (proven, 256thr) ==================
#define TILE_BYTES 16384
#define OFF_AH 0
#define OFF_AL (TILE_BYTES)
#define OFF_BH (2 * TILE_BYTES)
#define OFF_BL (3 * TILE_BYTES)
#define STAGE_BYTES (4 * TILE_BYTES)
#define NSTAGE 3
#define SMEM_CTX (NSTAGE * STAGE_BYTES)

__global__ void __launch_bounds__(256, 1)
ctx_gemm(const bf16* __restrict__ Ah, const bf16* __restrict__ Al,
         const bf16* __restrict__ Bh, const bf16* __restrict__ Bl,
         const float* __restrict__ bias, float* __restrict__ C,
         int M, int N, int K)
{
    extern __shared__ char smem[];
    const uint32_t sbase = smem_u32(smem);
    const int tid = threadIdx.x;
    const int wid = tid >> 5;
    const int lid = tid & 31;
    const int m0 = blockIdx.y * 128;
    const int n0 = blockIdx.x * 128;
    const int warp_m = (wid >> 2) * 64;
    const int warp_n = (wid & 3) * 32;

    float acc[4][4][4];
#pragma unroll
    for (int i = 0; i < 4; ++i)
#pragma unroll
        for (int j = 0; j < 4; ++j)
#pragma unroll
            for (int q = 0; q < 4; ++q) acc[i][j][q] = 0.f;

    auto load_stage = [&](int t, int buf) {
        const uint32_t bb = sbase + buf * STAGE_BYTES;
        const int k0 = t * 64;
        for (int i = tid; i < 1024; i += 256) {
            int row = i >> 3, c = i & 7;
            int m = m0 + row;
            uint32_t v = (m < M) ? 16u : 0u;
            size_t go = (size_t)(m < M ? m : 0) * K + k0 + c * 8;
            uint32_t so = SWZ(row * 128 + c * 16);
            cp16(bb + OFF_AH + so, Ah + go, v);
            cp16(bb + OFF_AL + so, Al + go, v);
        }
        for (int i = tid; i < 1024; i += 256) {
            int row = i >> 3, c = i & 7;
            size_t go = (size_t)(n0 + row) * K + k0 + c * 8;
            uint32_t so = SWZ(row * 128 + c * 16);
            cp16(bb + OFF_BH + so, Bh + go, 16u);
            cp16(bb + OFF_BL + so, Bl + go, 16u);
        }
        cp_commit();
    };

    const int nk = K / 64;
    load_stage(0, 0);
    if (nk > 1) load_stage(1, 1);

    for (int t = 0; t < nk; ++t) {
        if (t < nk - 1) cp_wait<1>(); else cp_wait<0>();
        __syncthreads();
        if (t + 2 < nk) load_stage(t + 2, (t + 2) % NSTAGE);

        const uint32_t bb = sbase + (t % NSTAGE) * STAGE_BYTES;
#pragma unroll
        for (int ks = 0; ks < 4; ++ks) {
            uint32_t ah[4][4], al[4][4], bh[4][2], bl[4][2];
            {
                uint32_t row_in = ((lid >> 3) & 1) * 8 + (lid & 7);
                uint32_t kb = ks * 32 + (lid >> 4) * 16;
#pragma unroll
                for (int mf = 0; mf < 4; ++mf) {
                    uint32_t off = SWZ((warp_m + mf * 16 + row_in) * 128 + kb);
                    ldm4(ah[mf], bb + OFF_AH + off);
                    ldm4(al[mf], bb + OFF_AL + off);
                }
            }
            {
                uint32_t row_in = ((lid >> 4) & 1) * 8 + (lid & 7);
                uint32_t kb = ks * 32 + ((lid >> 3) & 1) * 16;
#pragma unroll
                for (int p = 0; p < 2; ++p) {
                    uint32_t off = SWZ((warp_n + p * 16 + row_in) * 128 + kb);
                    uint32_t r[4];
                    ldm4(r, bb + OFF_BH + off);
                    bh[2 * p][0] = r[0]; bh[2 * p][1] = r[1];
                    bh[2 * p + 1][0] = r[2]; bh[2 * p + 1][1] = r[3];
                    ldm4(r, bb + OFF_BL + off);
                    bl[2 * p][0] = r[0]; bl[2 * p][1] = r[1];
                    bl[2 * p + 1][0] = r[2]; bl[2 * p + 1][1] = r[3];
                }
            }
#pragma unroll
            for (int mf = 0; mf < 4; ++mf)
#pragma unroll
                for (int nf = 0; nf < 4; ++nf)
                    mma_bf16(acc[mf][nf], ah[mf], bh[nf]);
#pragma unroll
            for (int mf = 0; mf < 4; ++mf)
#pragma unroll
                for (int nf = 0; nf < 4; ++nf)
                    mma_bf16(acc[mf][nf], ah[mf], bl[nf]);
#pragma unroll
            for (int mf = 0; mf < 4; ++mf)
#pragma unroll
                for (int nf = 0; nf < 4; ++nf)
                    mma_bf16(acc[mf][nf], al[mf], bh[nf]);
        }
        __syncthreads();
    }

#pragma unroll
    for (int mf = 0; mf < 4; ++mf) {
        int r0 = m0 + warp_m + mf * 16 + (lid >> 2);
#pragma unroll
        for (int nf = 0; nf < 4; ++nf) {
            int col = n0 + warp_n + nf * 8 + (lid & 3) * 2;
            float b0 = bias ? bias[col] : 0.f;
            float b1 = bias ? bias[col + 1] : 0.f;
            if (r0 < M) {
                float2 v = make_float2(acc[mf][nf][0] + b0, acc[mf][nf][1] + b1);
                *reinterpret_cast<float2*>(&C[(size_t)r0 * N + col]) = v;
            }
            if (r0 + 8 < M) {
                float2 v = make_float2(acc[mf][nf][2] + b0, acc[mf][nf][3] + b1);
                *reinterpret_cast<float2*>(&C[(size_t)(r0 + 8) * N + col]) = v;
            }
        }
    }
}

// ============ main GEMM: plain fp16 single pass, PERSISTENT ==================
// out = act_fp16 @ W_fp16^T, fp32 accumulate. Stage = 32 KB; 3 stages = 96 KB
// -> 2 CTAs/SM. 296 persistent CTAs loop over all (m,n) tiles.
#define MOFF_AH 0
#define MOFF_BH 16384
#define MSTAGE  32768
#define SMEM_MAIN (3 * 32768)     // 96 KB

__global__ void __launch_bounds__(256, 2)
main_gemm(const half* __restrict__ Ah, const half* __restrict__ Bh,
          float* __restrict__ C, int M, int ntiles)
{
    extern __shared__ char smem[];
    const uint32_t sbase = smem_u32(smem);
    const int tid = threadIdx.x;
    const int wid = tid >> 5;
    const int lid = tid & 31;
    const int warp_m = (wid >> 2) * 64;
    const int warp_n = (wid & 3) * 32;
    const int nk = K_TOTAL / 64;   // 48

    auto load_stage = [&](int m0, int n0, int t, int buf) {
        const uint32_t bb = sbase + buf * MSTAGE;
        const int k0 = t * 64;
        for (int i = tid; i < 1024; i += 256) {
            int row = i >> 3, c = i & 7;
            int m = m0 + row;
            uint32_t v = (m < M) ? 16u : 0u;
            uint32_t so = SWZ(row * 128 + c * 16);
            cp16(bb + MOFF_AH + so,
                 Ah + (size_t)(m < M ? m : 0) * K_TOTAL + k0 + c * 8, v);
        }
        for (int i = tid; i < 1024; i += 256) {
            int row = i >> 3, c = i & 7;
            size_t go = (size_t)(n0 + row) * K_TOTAL + k0 + c * 8;
            uint32_t so = SWZ(row * 128 + c * 16);
            cp16(bb + MOFF_BH + so, Bh + go, 16u);
        }
        cp_commit();
    };

    for (int tile = blockIdx.x; tile < ntiles; tile += gridDim.x) {
        const int m0 = (tile >> 1) * 128;
        const int n0 = (tile & 1) * 128;

        float acc[4][4][4];
#pragma unroll
        for (int i = 0; i < 4; ++i)
#pragma unroll
            for (int j = 0; j < 4; ++j)
#pragma unroll
                for (int q = 0; q < 4; ++q) acc[i][j][q] = 0.f;

        load_stage(m0, n0, 0, 0);
        load_stage(m0, n0, 1, 1);

        for (int t = 0; t < nk; ++t) {
            if (t < nk - 1) cp_wait<1>(); else cp_wait<0>();
            __syncthreads();   // stage t ready; all warps done with stage t-1
            if (t + 2 < nk) load_stage(m0, n0, t + 2, (t + 2) % 3);

            const uint32_t bb = sbase + (t % 3) * MSTAGE;
#pragma unroll
            for (int ks = 0; ks < 4; ++ks) {
                uint32_t ah[4][4], bh[4][2];
                {
                    uint32_t row_in = ((lid >> 3) & 1) * 8 + (lid & 7);
                    uint32_t kb = ks * 32 + (lid >> 4) * 16;
#pragma unroll
                    for (int mf = 0; mf < 4; ++mf) {
                        uint32_t off = SWZ((warp_m + mf * 16 + row_in) * 128 + kb);
                        ldm4(ah[mf], bb + MOFF_AH + off);
                    }
                }
                {
                    uint32_t row_in = ((lid >> 4) & 1) * 8 + (lid & 7);
                    uint32_t kb = ks * 32 + ((lid >> 3) & 1) * 16;
#pragma unroll
                    for (int p = 0; p < 2; ++p) {
                        uint32_t off = SWZ((warp_n + p * 16 + row_in) * 128 + kb);
                        uint32_t r[4];
                        ldm4(r, bb + MOFF_BH + off);
                        bh[2 * p][0] = r[0]; bh[2 * p][1] = r[1];
                        bh[2 * p + 1][0] = r[2]; bh[2 * p + 1][1] = r[3];
                    }
                }
#pragma unroll
                for (int mf = 0; mf < 4; ++mf)
#pragma unroll
                    for (int nf = 0; nf < 4; ++nf)
                        mma_f16(acc[mf][nf], ah[mf], bh[nf]);
            }
        }

        // epilogue (no smem) — overlaps with next tile's prologue loads
#pragma unroll
        for (int mf = 0; mf < 4; ++mf) {
            int r0 = m0 + warp_m + mf * 16 + (lid >> 2);
#pragma unroll
            for (int nf = 0; nf < 4; ++nf) {
                int col = n0 + warp_n + nf * 8 + (lid & 3) * 2;
                if (r0 < M) {
                    float2 v = make_float2(acc[mf][nf][0], acc[mf][nf][1]);
                    *reinterpret_cast<float2*>(&C[(size_t)r0 * OUT_DIM + col]) = v;
                }
                if (r0 + 8 < M) {
                    float2 v = make_float2(acc[mf][nf][2], acc[mf][nf][3]);
                    *reinterpret_cast<float2*>(&C[(size_t)(r0 + 8) * OUT_DIM + col]) = v;
                }
            }
        }
    }
}

// ---------------- activation builder: vectorized, cardinal spline -----------
// 8 consecutive i per thread; float4 reads; uint4 coalesced stores.
// Cardinal cubic closed form (verified in R5 against reference).
__global__ void build_act(const float* __restrict__ node, const float* __restrict__ xc,
                          const int* __restrict__ pairs, const float* __restrict__ gridp,
                          half* __restrict__ acth, int nEdges)
{
    int t = blockIdx.x * blockDim.x + threadIdx.x;
    if (t >= nEdges * 48) return;
    int n = t / 48;
    int sub = t - n * 48;
    int i0 = sub * 8;

    const float g0 = gridp[0];
    const float rh = 1.f / (gridp[1] - g0);

    const float* src;
    if (i0 < NODE_DIM)
        src = node + (size_t)pairs[2 * n] * NODE_DIM + i0;
    else if (i0 < 2 * NODE_DIM)
        src = node + (size_t)pairs[2 * n + 1] * NODE_DIM + (i0 - NODE_DIM);
    else
        src = xc + (size_t)n * NODE_DIM + (i0 - 2 * NODE_DIM);

    float4 xa = *reinterpret_cast<const float4*>(src);
    float4 xb = *reinterpret_cast<const float4*>(src + 4);
    float xs[8] = {xa.x, xa.y, xa.z, xa.w, xb.x, xb.y, xb.z, xb.w};

    uint32_t so[4];
    uint32_t co[N_COEF][4];

#pragma unroll
    for (int q = 0; q < 4; ++q) {
        float w0[N_COEF], w1[N_COEF];
        float s0, s1;
#pragma unroll
        for (int h = 0; h < 2; ++h) {
            float x = xs[2 * q + h];
            float s = x / (1.f + __expf(-x));
            float d = (x - g0) * rh;
            float fj = floorf(d);
            int js = (int)fj;
            float u = d - fj;
            bool inr = (d >= 0.f) && (js <= 9);
            float u2 = u * u, u3 = u2 * u;
            float om = 1.f - u;
            float c0 = om * om * om * (1.f / 6.f);
            float c1 = (3.f * u3 - 6.f * u2 + 4.f) * (1.f / 6.f);
            float c2 = (-3.f * u3 + 3.f * u2 + 3.f * u + 1.f) * (1.f / 6.f);
            float c3 = u3 * (1.f / 6.f);
            float* w = h ? w1 : w0;
#pragma unroll
            for (int j = 0; j < N_COEF; ++j) {
                int r = j - js + 3;
                float v = 0.f;
                v = (r == 0) ? c0 : v;
                v = (r == 1) ? c1 : v;
                v = (r == 2) ? c2 : v;
                v = (r == 3) ? c3 : v;
                w[j] = inr ? v : 0.f;
            }
            if (h) s1 = s; else s0 = s;
        }
        so[q] = pack_half2(s0, s1);
#pragma unroll
        for (int j = 0; j < N_COEF; ++j)
            co[j][q] = pack_half2(w0[j], w1[j]);
    }

    size_t base = (size_t)n * K_TOTAL;
    *reinterpret_cast<uint4*>(acth + base + i0) =
        make_uint4(so[0], so[1], so[2], so[3]);
#pragma unroll
    for (int c = 0; c < N_COEF; ++c)
        *reinterpret_cast<uint4*>(acth + base + IN_DIM + (size_t)c * IN_DIM + i0) =
            make_uint4(co[c][0], co[c][1], co[c][2], co[c][3]);
}

// ---------------------------------------------------------------------------
extern "C" void kernel_launch(void* const* d_in, const int* in_sizes, int n_in,
                              void* d_out, int out_size)
{
    const float* node  = (const float*)d_in[0];
    const float* cemb  = (const float*)d_in[1];
    const int*   pairs = (const int*)  d_in[2];
    const float* ctxw  = (const float*)d_in[3];
    const float* ctxb  = (const float*)d_in[4];
    const float* bw    = (const float*)d_in[5];
    const float* sw    = (const float*)d_in[6];
    const float* ss    = (const float*)d_in[7];
    const float* grid  = (const float*)d_in[8];
    float* out = (float*)d_out;

    int nEdges = in_sizes[2] / 2;

    float *xc;
    half *acth, *wh;
    bf16 *ceh, *cel, *cwh, *cwl;
    cudaGetSymbolAddress((void**)&xc, g_xc);
    cudaGetSymbolAddress((void**)&acth, g_act_h);
    cudaGetSymbolAddress((void**)&wh, g_w_h);
    cudaGetSymbolAddress((void**)&ceh, g_cemb_hi);
    cudaGetSymbolAddress((void**)&cel, g_cemb_lo);
    cudaGetSymbolAddress((void**)&cwh, g_cw_hi);
    cudaGetSymbolAddress((void**)&cwl, g_cw_lo);

    cudaFuncSetAttribute(ctx_gemm, cudaFuncAttributeMaxDynamicSharedMemorySize, SMEM_CTX);
    cudaFuncSetAttribute(main_gemm, cudaFuncAttributeMaxDynamicSharedMemorySize, SMEM_MAIN);

    {
        int total = OUT_DIM * K_TOTAL;
        prep_weff<<<(total + 255) / 256, 256>>>(bw, sw, ss, wh);
    }
    {
        size_t n4 = (size_t)NODE_DIM * CTX_DIM / 4;
        cvt_split4<<<(int)((n4 + 255) / 256), 256>>>(ctxw, cwh, cwl, n4);
    }
    {
        size_t n4 = (size_t)nEdges * CTX_DIM / 4;
        cvt_split4<<<(int)((n4 + 255) / 256), 256>>>(cemb, ceh, cel, n4);
    }

    // ctx projection  xc = cemb @ ctxw^T + b  (M=nEdges, N=128, K=256)
    {
        dim3 g(1, (nEdges + 127) / 128);
        ctx_gemm<<<g, 256, SMEM_CTX>>>(ceh, cel, cwh, cwl, ctxb, xc,
                                       nEdges, NODE_DIM, CTX_DIM);
    }

    // activations (fp16, vectorized)
    {
        int total = nEdges * 48;
        build_act<<<(total + 255) / 256, 256>>>(node, xc, pairs, grid, acth, nEdges);
    }

    // main GEMM  out = act @ weff^T  (M=nEdges, N=256, K=3072), persistent
    {
        int ntiles = ((nEdges + 127) / 128) * 2;
        int blocks = ntiles < 296 ? ntiles : 296;
        main_gemm<<<blocks, 256, SMEM_MAIN>>>(acth, wh, out, nEdges, ntiles);
    }
}

// round 13
// speedup vs baseline: 3.7722x; 1.0461x over previous
#include <cuda_runtime.h>
#include <cuda_bf16.h>
#include <cuda_fp16.h>
#include <cstdint>

// ---------------- problem constants ----------------
#define NODE_DIM 128
#define CTX_DIM  256
#define OUT_DIM  256
#define IN_DIM   384
#define N_COEF   7
#define K_TOTAL  3072        // coefficient-major: k<384 silu, k>=384: c*384+i
#define MAX_EDGES 100000

// ---------------- device scratch (static) ----------------
__device__ float g_xc[(size_t)MAX_EDGES * NODE_DIM];
__device__ half  g_act_h[(size_t)MAX_EDGES * K_TOTAL];    // 614 MB
__device__ half  g_w_h[(size_t)OUT_DIM * K_TOTAL];
__device__ half  g_cemb_h[(size_t)MAX_EDGES * CTX_DIM];   // 51 MB
__device__ half  g_cw_h[(size_t)NODE_DIM * CTX_DIM];
__device__ half  g_cw_l[(size_t)NODE_DIM * CTX_DIM];

// ---------------- helpers ----------------
__device__ __forceinline__ uint32_t smem_u32(const void* p) {
    uint32_t a;
    asm("{ .reg .u64 t; cvta.to.shared.u64 t, %1; cvt.u32.u64 %0, t; }" : "=r"(a) : "l"(p));
    return a;
}
#define SWZ(x) ((x) ^ (((x) >> 3) & 0x70))

__device__ __forceinline__ void cp16(uint32_t saddr, const void* g, uint32_t sz) {
    asm volatile("cp.async.cg.shared.global [%0], [%1], 16, %2;\n"
                 :: "r"(saddr), "l"(g), "r"(sz));
}
template <int N>
__device__ __forceinline__ void cp_wait() {
    asm volatile("cp.async.wait_group %0;\n" :: "n"(N) : "memory");
}
__device__ __forceinline__ void cp_commit() {
    asm volatile("cp.async.commit_group;\n" ::: "memory");
}

__device__ __forceinline__ void ldm4(uint32_t* r, uint32_t addr) {
    asm volatile("ldmatrix.sync.aligned.m8n8.x4.shared.b16 {%0,%1,%2,%3}, [%4];"
                 : "=r"(r[0]), "=r"(r[1]), "=r"(r[2]), "=r"(r[3]) : "r"(addr));
}

__device__ __forceinline__ void mma_f16(float* d, const uint32_t* a, const uint32_t* b) {
    asm volatile(
        "mma.sync.aligned.m16n8k16.row.col.f32.f16.f16.f32 "
        "{%0,%1,%2,%3}, {%4,%5,%6,%7}, {%8,%9}, {%0,%1,%2,%3};"
        : "+f"(d[0]), "+f"(d[1]), "+f"(d[2]), "+f"(d[3])
        : "r"(a[0]), "r"(a[1]), "r"(a[2]), "r"(a[3]), "r"(b[0]), "r"(b[1]));
}

__device__ __forceinline__ uint32_t pack_half2(float lo, float hi) {
    __half2 h;
    h.x = __float2half_rn(lo);
    h.y = __float2half_rn(hi);
    return *reinterpret_cast<uint32_t*>(&h);
}

// ---------------- fused prep: weff fp16 + ctxw fp16 hi/lo + cemb fp16 -------
__global__ void prep_all(const float* __restrict__ bw, const float* __restrict__ sw,
                         const float* __restrict__ ss, half* __restrict__ Wh,
                         const float* __restrict__ ctxw, half* __restrict__ cwh,
                         half* __restrict__ cwl,
                         const float* __restrict__ cemb, half* __restrict__ ceh,
                         int nCemb8)
{
    int t = blockIdx.x * blockDim.x + threadIdx.x;
    const int T1 = OUT_DIM * K_TOTAL;            // 786432
    const int T2 = (NODE_DIM * CTX_DIM) / 4;     // 8192

    if (t < T1) {
        int o = t / K_TOTAL;
        int k = t - o * K_TOTAL;
        float v;
        if (k < IN_DIM) v = bw[o * IN_DIM + k];
        else {
            int r = k - IN_DIM;
            int c = r / IN_DIM;
            int i = r - c * IN_DIM;
            v = sw[((size_t)o * IN_DIM + i) * N_COEF + c] * ss[o * IN_DIM + i];
        }
        Wh[t] = __float2half_rn(v);
        return;
    }
    t -= T1;
    if (t < T2) {
        float4 v = *reinterpret_cast<const float4*>(ctxw + t * 4);
        float f[4] = {v.x, v.y, v.z, v.w};
        float h[4], l[4];
#pragma unroll
        for (int q = 0; q < 4; ++q) {
            half b = __float2half_rn(f[q]);
            h[q] = __half2float(b);
            l[q] = f[q] - h[q];
        }
        *reinterpret_cast<uint2*>(cwh + t * 4) =
            make_uint2(pack_half2(h[0], h[1]), pack_half2(h[2], h[3]));
        *reinterpret_cast<uint2*>(cwl + t * 4) =
            make_uint2(pack_half2(l[0], l[1]), pack_half2(l[2], l[3]));
        return;
    }
    t -= T2;
    if (t < nCemb8) {
        const float4* p = reinterpret_cast<const float4*>(cemb) + (size_t)t * 2;
        float4 a = p[0], b = p[1];
        uint4 o;
        o.x = pack_half2(a.x, a.y);
        o.y = pack_half2(a.z, a.w);
        o.z = pack_half2(b.x, b.y);
        o.w = pack_half2(b.z, b.w);
        *reinterpret_cast<uint4*>(ceh + (size_t)t * 8) = o;
    }
}

// ============ ctx GEMM: fp16 2-pass (A plain, B hi/lo corrected) ============
// xc = cemb @ ctxw^T + bias.  BM=128, BN=128, BK=64, 256 thr, 3 stages.
#define COFF_A  0
#define COFF_BH 16384
#define COFF_BL 32768
#define CSTAGE  49152
#define SMEM_CTX (3 * 49152)      // 144 KB

__global__ void __launch_bounds__(256, 1)
ctx_gemm(const half* __restrict__ A, const half* __restrict__ Bh,
         const half* __restrict__ Bl, const float* __restrict__ bias,
         float* __restrict__ C, int M, int N, int K)
{
    extern __shared__ char smem[];
    const uint32_t sbase = smem_u32(smem);
    const int tid = threadIdx.x;
    const int wid = tid >> 5;
    const int lid = tid & 31;
    const int m0 = blockIdx.y * 128;
    const int n0 = blockIdx.x * 128;
    const int warp_m = (wid >> 2) * 64;
    const int warp_n = (wid & 3) * 32;

    float acc[4][4][4];
#pragma unroll
    for (int i = 0; i < 4; ++i)
#pragma unroll
        for (int j = 0; j < 4; ++j)
#pragma unroll
            for (int q = 0; q < 4; ++q) acc[i][j][q] = 0.f;

    auto load_stage = [&](int t, int buf) {
        const uint32_t bb = sbase + buf * CSTAGE;
        const int k0 = t * 64;
        for (int i = tid; i < 1024; i += 256) {
            int row = i >> 3, c = i & 7;
            int m = m0 + row;
            uint32_t v = (m < M) ? 16u : 0u;
            size_t go = (size_t)(m < M ? m : 0) * K + k0 + c * 8;
            uint32_t so = SWZ(row * 128 + c * 16);
            cp16(bb + COFF_A + so, A + go, v);
        }
        for (int i = tid; i < 1024; i += 256) {
            int row = i >> 3, c = i & 7;
            size_t go = (size_t)(n0 + row) * K + k0 + c * 8;
            uint32_t so = SWZ(row * 128 + c * 16);
            cp16(bb + COFF_BH + so, Bh + go, 16u);
            cp16(bb + COFF_BL + so, Bl + go, 16u);
        }
        cp_commit();
    };

    const int nk = K / 64;
    load_stage(0, 0);
    if (nk > 1) load_stage(1, 1);

    for (int t = 0; t < nk; ++t) {
        if (t < nk - 1) cp_wait<1>(); else cp_wait<0>();
        __syncthreads();
        if (t + 2 < nk) load_stage(t + 2, (t + 2) % 3);

        const uint32_t bb = sbase + (t % 3) * CSTAGE;
#pragma unroll
        for (int ks = 0; ks < 4; ++ks) {
            uint32_t ah[4][4], bh[4][2], bl[4][2];
            {
                uint32_t row_in = ((lid >> 3) & 1) * 8 + (lid & 7);
                uint32_t kb = ks * 32 + (lid >> 4) * 16;
#pragma unroll
                for (int mf = 0; mf < 4; ++mf) {
                    uint32_t off = SWZ((warp_m + mf * 16 + row_in) * 128 + kb);
                    ldm4(ah[mf], bb + COFF_A + off);
                }
            }
            {
                uint32_t row_in = ((lid >> 4) & 1) * 8 + (lid & 7);
                uint32_t kb = ks * 32 + ((lid >> 3) & 1) * 16;
#pragma unroll
                for (int p = 0; p < 2; ++p) {
                    uint32_t off = SWZ((warp_n + p * 16 + row_in) * 128 + kb);
                    uint32_t r[4];
                    ldm4(r, bb + COFF_BH + off);
                    bh[2 * p][0] = r[0]; bh[2 * p][1] = r[1];
                    bh[2 * p + 1][0] = r[2]; bh[2 * p + 1][1] = r[3];
                    ldm4(r, bb + COFF_BL + off);
                    bl[2 * p][0] = r[0]; bl[2 * p][1] = r[1];
                    bl[2 * p + 1][0] = r[2]; bl[2 * p + 1][1] = r[3];
                }
            }
#pragma unroll
            for (int mf = 0; mf < 4; ++mf)
#pragma unroll
                for (int nf = 0; nf < 4; ++nf)
                    mma_f16(acc[mf][nf], ah[mf], bh[nf]);
#pragma unroll
            for (int mf = 0; mf < 4; ++mf)
#pragma unroll
                for (int nf = 0; nf < 4; ++nf)
                    mma_f16(acc[mf][nf], ah[mf], bl[nf]);
        }
        __syncthreads();
    }

#pragma unroll
    for (int mf = 0; mf < 4; ++mf) {
        int r0 = m0 + warp_m + mf * 16 + (lid >> 2);
#pragma unroll
        for (int nf = 0; nf < 4; ++nf) {
            int col = n0 + warp_n + nf * 8 + (lid & 3) * 2;
            float b0 = bias ? bias[col] : 0.f;
            float b1 = bias ? bias[col + 1] : 0.f;
            if (r0 < M) {
                float2 v = make_float2(acc[mf][nf][0] + b0, acc[mf][nf][1] + b1);
                *reinterpret_cast<float2*>(&C[(size_t)r0 * N + col]) = v;
            }
            if (r0 + 8 < M) {
                float2 v = make_float2(acc[mf][nf][2] + b0, acc[mf][nf][3] + b1);
                *reinterpret_cast<float2*>(&C[(size_t)(r0 + 8) * N + col]) = v;
            }
        }
    }
}

// ============ main GEMM: plain fp16 single pass, PERSISTENT ==================
#define MOFF_AH 0
#define MOFF_BH 16384
#define MSTAGE  32768
#define SMEM_MAIN (3 * 32768)     // 96 KB -> 2 CTAs/SM

__global__ void __launch_bounds__(256, 2)
main_gemm(const half* __restrict__ Ah, const half* __restrict__ Bh,
          float* __restrict__ C, int M, int ntiles)
{
    extern __shared__ char smem[];
    const uint32_t sbase = smem_u32(smem);
    const int tid = threadIdx.x;
    const int wid = tid >> 5;
    const int lid = tid & 31;
    const int warp_m = (wid >> 2) * 64;
    const int warp_n = (wid & 3) * 32;
    const int nk = K_TOTAL / 64;   // 48

    auto load_stage = [&](int m0, int n0, int t, int buf) {
        const uint32_t bb = sbase + buf * MSTAGE;
        const int k0 = t * 64;
        for (int i = tid; i < 1024; i += 256) {
            int row = i >> 3, c = i & 7;
            int m = m0 + row;
            uint32_t v = (m < M) ? 16u : 0u;
            uint32_t so = SWZ(row * 128 + c * 16);
            cp16(bb + MOFF_AH + so,
                 Ah + (size_t)(m < M ? m : 0) * K_TOTAL + k0 + c * 8, v);
        }
        for (int i = tid; i < 1024; i += 256) {
            int row = i >> 3, c = i & 7;
            size_t go = (size_t)(n0 + row) * K_TOTAL + k0 + c * 8;
            uint32_t so = SWZ(row * 128 + c * 16);
            cp16(bb + MOFF_BH + so, Bh + go, 16u);
        }
        cp_commit();
    };

    for (int tile = blockIdx.x; tile < ntiles; tile += gridDim.x) {
        const int m0 = (tile >> 1) * 128;
        const int n0 = (tile & 1) * 128;

        float acc[4][4][4];
#pragma unroll
        for (int i = 0; i < 4; ++i)
#pragma unroll
            for (int j = 0; j < 4; ++j)
#pragma unroll
                for (int q = 0; q < 4; ++q) acc[i][j][q] = 0.f;

        load_stage(m0, n0, 0, 0);
        load_stage(m0, n0, 1, 1);

        for (int t = 0; t < nk; ++t) {
            if (t < nk - 1) cp_wait<1>(); else cp_wait<0>();
            __syncthreads();
            if (t + 2 < nk) load_stage(m0, n0, t + 2, (t + 2) % 3);

            const uint32_t bb = sbase + (t % 3) * MSTAGE;
#pragma unroll
            for (int ks = 0; ks < 4; ++ks) {
                uint32_t ah[4][4], bh[4][2];
                {
                    uint32_t row_in = ((lid >> 3) & 1) * 8 + (lid & 7);
                    uint32_t kb = ks * 32 + (lid >> 4) * 16;
#pragma unroll
                    for (int mf = 0; mf < 4; ++mf) {
                        uint32_t off = SWZ((warp_m + mf * 16 + row_in) * 128 + kb);
                        ldm4(ah[mf], bb + MOFF_AH + off);
                    }
                }
                {
                    uint32_t row_in = ((lid >> 4) & 1) * 8 + (lid & 7);
                    uint32_t kb = ks * 32 + ((lid >> 3) & 1) * 16;
#pragma unroll
                    for (int p = 0; p < 2; ++p) {
                        uint32_t off = SWZ((warp_n + p * 16 + row_in) * 128 + kb);
                        uint32_t r[4];
                        ldm4(r, bb + MOFF_BH + off);
                        bh[2 * p][0] = r[0]; bh[2 * p][1] = r[1];
                        bh[2 * p + 1][0] = r[2]; bh[2 * p + 1][1] = r[3];
                    }
                }
#pragma unroll
                for (int mf = 0; mf < 4; ++mf)
#pragma unroll
                    for (int nf = 0; nf < 4; ++nf)
                        mma_f16(acc[mf][nf], ah[mf], bh[nf]);
            }
        }

#pragma unroll
        for (int mf = 0; mf < 4; ++mf) {
            int r0 = m0 + warp_m + mf * 16 + (lid >> 2);
#pragma unroll
            for (int nf = 0; nf < 4; ++nf) {
                int col = n0 + warp_n + nf * 8 + (lid & 3) * 2;
                if (r0 < M) {
                    float2 v = make_float2(acc[mf][nf][0], acc[mf][nf][1]);
                    *reinterpret_cast<float2*>(&C[(size_t)r0 * OUT_DIM + col]) = v;
                }
                if (r0 + 8 < M) {
                    float2 v = make_float2(acc[mf][nf][2], acc[mf][nf][3]);
                    *reinterpret_cast<float2*>(&C[(size_t)(r0 + 8) * OUT_DIM + col]) = v;
                }
            }
        }
    }
}

// ---------------- activation builder: vectorized, cardinal spline -----------
__global__ void build_act(const float* __restrict__ node, const float* __restrict__ xc,
                          const int* __restrict__ pairs, const float* __restrict__ gridp,
                          half* __restrict__ acth, int nEdges)
{
    int t = blockIdx.x * blockDim.x + threadIdx.x;
    if (t >= nEdges * 48) return;
    int n = t / 48;
    int sub = t - n * 48;
    int i0 = sub * 8;

    const float g0 = gridp[0];
    const float rh = 1.f / (gridp[1] - g0);

    const float* src;
    if (i0 < NODE_DIM)
        src = node + (size_t)pairs[2 * n] * NODE_DIM + i0;
    else if (i0 < 2 * NODE_DIM)
        src = node + (size_t)pairs[2 * n + 1] * NODE_DIM + (i0 - NODE_DIM);
    else
        src = xc + (size_t)n * NODE_DIM + (i0 - 2 * NODE_DIM);

    float4 xa = *reinterpret_cast<const float4*>(src);
    float4 xb = *reinterpret_cast<const float4*>(src + 4);
    float xs[8] = {xa.x, xa.y, xa.z, xa.w, xb.x, xb.y, xb.z, xb.w};

    uint32_t so[4];
    uint32_t co[N_COEF][4];

#pragma unroll
    for (int q = 0; q < 4; ++q) {
        float w0[N_COEF], w1[N_COEF];
        float s0, s1;
#pragma unroll
        for (int h = 0; h < 2; ++h) {
            float x = xs[2 * q + h];
            float s = x / (1.f + __expf(-x));
            float d = (x - g0) * rh;
            float fj = floorf(d);
            int js = (int)fj;
            float u = d - fj;
            bool inr = (d >= 0.f) && (js <= 9);
            float u2 = u * u, u3 = u2 * u;
            float om = 1.f - u;
            float c0 = om * om * om * (1.f / 6.f);
            float c1 = (3.f * u3 - 6.f * u2 + 4.f) * (1.f / 6.f);
            float c2 = (-3.f * u3 + 3.f * u2 + 3.f * u + 1.f) * (1.f / 6.f);
            float c3 = u3 * (1.f / 6.f);
            float* w = h ? w1 : w0;
#pragma unroll
            for (int j = 0; j < N_COEF; ++j) {
                int r = j - js + 3;
                float v = 0.f;
                v = (r == 0) ? c0 : v;
                v = (r == 1) ? c1 : v;
                v = (r == 2) ? c2 : v;
                v = (r == 3) ? c3 : v;
                w[j] = inr ? v : 0.f;
            }
            if (h) s1 = s; else s0 = s;
        }
        so[q] = pack_half2(s0, s1);
#pragma unroll
        for (int j = 0; j < N_COEF; ++j)
            co[j][q] = pack_half2(w0[j], w1[j]);
    }

    size_t base = (size_t)n * K_TOTAL;
    *reinterpret_cast<uint4*>(acth + base + i0) =
        make_uint4(so[0], so[1], so[2], so[3]);
#pragma unroll
    for (int c = 0; c < N_COEF; ++c)
        *reinterpret_cast<uint4*>(acth + base + IN_DIM + (size_t)c * IN_DIM + i0) =
            make_uint4(co[c][0], co[c][1], co[c][2], co[c][3]);
}

// ---------------------------------------------------------------------------
extern "C" void kernel_launch(void* const* d_in, const int* in_sizes, int n_in,
                              void* d_out, int out_size)
{
    const float* node  = (const float*)d_in[0];
    const float* cemb  = (const float*)d_in[1];
    const int*   pairs = (const int*)  d_in[2];
    const float* ctxw  = (const float*)d_in[3];
    const float* ctxb  = (const float*)d_in[4];
    const float* bw    = (const float*)d_in[5];
    const float* sw    = (const float*)d_in[6];
    const float* ss    = (const float*)d_in[7];
    const float* grid  = (const float*)d_in[8];
    float* out = (float*)d_out;

    int nEdges = in_sizes[2] / 2;

    float *xc;
    half *acth, *wh, *ceh, *cwh, *cwl;
    cudaGetSymbolAddress((void**)&xc, g_xc);
    cudaGetSymbolAddress((void**)&acth, g_act_h);
    cudaGetSymbolAddress((void**)&wh, g_w_h);
    cudaGetSymbolAddress((void**)&ceh, g_cemb_h);
    cudaGetSymbolAddress((void**)&cwh, g_cw_h);
    cudaGetSymbolAddress((void**)&cwl, g_cw_l);

    cudaFuncSetAttribute(ctx_gemm, cudaFuncAttributeMaxDynamicSharedMemorySize, SMEM_CTX);
    cudaFuncSetAttribute(main_gemm, cudaFuncAttributeMaxDynamicSharedMemorySize, SMEM_MAIN);

    // fused prep: weights + ctxw split + cemb convert
    {
        int nCemb8 = nEdges * CTX_DIM / 8;
        int total = OUT_DIM * K_TOTAL + (NODE_DIM * CTX_DIM) / 4 + nCemb8;
        prep_all<<<(total + 255) / 256, 256>>>(bw, sw, ss, wh, ctxw, cwh, cwl,
                                               cemb, ceh, nCemb8);
    }

    // ctx projection  xc = cemb @ ctxw^T + b  (M=nEdges, N=128, K=256)
    {
        dim3 g(1, (nEdges + 127) / 128);
        ctx_gemm<<<g, 256, SMEM_CTX>>>(ceh, cwh, cwl, ctxb, xc,
                                       nEdges, NODE_DIM, CTX_DIM);
    }

    // activations (fp16, vectorized)
    {
        int total = nEdges * 48;
        build_act<<<(total + 255) / 256, 256>>>(node, xc, pairs, grid, acth, nEdges);
    }

    // main GEMM  out = act @ weff^T  (M=nEdges, N=256, K=3072), persistent
    {
        int ntiles = ((nEdges + 127) / 128) * 2;
        int blocks = ntiles < 296 ? ntiles : 296;
        main_gemm<<<blocks, 256, SMEM_MAIN>>>(acth, wh, out, nEdges, ntiles);
    }
}